// round 13
// baseline (speedup 1.0000x reference)
#include <cuda_runtime.h>
#include <cuda_fp16.h>
#include <math.h>
#include <stdint.h>

#define NB 2
#define NL 2048
#define NK 48
#define NH 128
#define NTOK (NB*NL)
#define NEDGE (NB*NL*NK)
#define FFH 512

__device__ int   g_idx32[NEDGE];
__device__ float g_h1 [NTOK*NH];
__device__ uint32_t g_h1f16[NTOK*NH/2];
__device__ uint32_t g_hEf16[NEDGE*NH/2];
__device__ uint32_t g_Hhi[NTOK*FFH/2];
__device__ uint32_t g_P1 [NTOK*64];
__device__ uint32_t g_G1 [NTOK*64];
__device__ uint32_t g_P2 [NTOK*64];
__device__ uint32_t g_G2 [NTOK*64];
__device__ float g_partA[NTOK*NH];
__device__ float g_partB[NTOK*NH];
// 18 fp16 matrices [k][n] (128x128), rows padded to 272B -> 2176 uint4 each
// 0-2 node MLP, 3-5 edge MLP, 6-9 Wi col-tiles, 10-13 Wo k-chunks,
// 14 W1-P, 15 W1-G, 16 W11-P, 17 W11-G
__device__ uint4 g_Wb[18*2176];

#define AST 272
// 64-row tile layout (hi-only A)
#define M_A   0
#define M_B   17408
#define M_STAT 52224
#define SMEM64 54272
#define SMEMNF 54784

__device__ __forceinline__ float gelu_f(float x) {
    return 0.5f * x * (1.0f + erff(x * 0.7071067811865475f));
}

__device__ __forceinline__ uint32_t smem_u32(const void* p) {
    uint32_t a;
    asm("{ .reg .u64 t; cvta.to.shared.u64 t, %1; cvt.u32.u64 %0, t; }"
        : "=r"(a) : "l"(p));
    return a;
}

__device__ __forceinline__ uint32_t pack_f16(float v0, float v1) {
    __half2 h = __floats2half2_rn(v0, v1);
    return *(uint32_t*)&h;
}

__device__ __forceinline__ float2 unpack_f16(uint32_t u) {
    return __half22float2(*(__half2*)&u);
}

__device__ __forceinline__ void cp16(uint32_t dst, const void* src) {
    asm volatile("cp.async.cg.shared.global [%0], [%1], 16;"
        :: "r"(dst), "l"(src));
}
#define CP_COMMIT() asm volatile("cp.async.commit_group;" ::: "memory")
#define CP_WAIT0()  asm volatile("cp.async.wait_group 0;" ::: "memory")
#define PREF_L2(p)  asm volatile("prefetch.global.L2 [%0];" :: "l"(p))

__device__ __forceinline__ void ldm4(uint32_t r[4], uint32_t a) {
    asm volatile("ldmatrix.sync.aligned.m8n8.x4.shared.b16 {%0,%1,%2,%3}, [%4];"
        : "=r"(r[0]), "=r"(r[1]), "=r"(r[2]), "=r"(r[3]) : "r"(a));
}
__device__ __forceinline__ void ldm4t(uint32_t r[4], uint32_t a) {
    asm volatile("ldmatrix.sync.aligned.m8n8.x4.trans.shared.b16 {%0,%1,%2,%3}, [%4];"
        : "=r"(r[0]), "=r"(r[1]), "=r"(r[2]), "=r"(r[3]) : "r"(a));
}
__device__ __forceinline__ void mma_f16(float c[4], const uint32_t a[4],
                                        uint32_t b0, uint32_t b1) {
    asm volatile(
        "mma.sync.aligned.m16n8k16.row.col.f32.f16.f16.f32 "
        "{%0,%1,%2,%3}, {%4,%5,%6,%7}, {%8,%9}, {%0,%1,%2,%3};"
        : "+f"(c[0]), "+f"(c[1]), "+f"(c[2]), "+f"(c[3])
        : "r"(a[0]), "r"(a[1]), "r"(a[2]), "r"(a[3]), "r"(b0), "r"(b1));
}

// ---------------------------------------------------------------------------
// convert: dtype detect (per-block, redundant) + normalize E_idx to int32.
// Indices are in [0,2048): if data is int64, all odd 32-bit words of the
// first 256 are zero; if int32, some odd word is a (nonzero) index a.s.
// ---------------------------------------------------------------------------
__global__ void convert_kernel(const void* __restrict__ e) {
    __shared__ int s_is64;
    if (threadIdx.x == 0) {
        const int* w = (const int*)e;
        int nz = 0;
        #pragma unroll 8
        for (int i = 1; i < 256; i += 2) nz |= (w[i] != 0);
        s_is64 = (nz == 0);
    }
    __syncthreads();
    int i = blockIdx.x * blockDim.x + threadIdx.x;
    if (i >= NEDGE) return;
    if (s_is64) g_idx32[i] = (int)((const long long*)e)[i];
    else        g_idx32[i] = ((const int*)e)[i];
}

// ---------------------------------------------------------------------------
// wprep: all weights -> fp16 tiles [k][n], rows padded to 272B.
// ---------------------------------------------------------------------------
__global__ void wprep_kernel(const float* W0, const float* W1, const float* W2,
                             const float* W3, const float* W4, const float* W5,
                             const float* Wi, const float* Wo,
                             const float* W1full, const float* W11full) {
    int gid = blockIdx.x * 256 + threadIdx.x;
    if (gid >= 18 * 16384) return;
    int m = gid >> 14, rem = gid & 16383;
    int k = rem >> 7, n = rem & 127;
    float v;
    if (m < 6) {
        const float* W = (m == 0) ? W0 : (m == 1) ? W1 : (m == 2) ? W2
                       : (m == 3) ? W3 : (m == 4) ? W4 : W5;
        v = W[k * 128 + n];
    } else if (m < 10) {
        v = Wi[k * FFH + (m - 6) * 128 + n];
    } else if (m < 14) {
        v = Wo[((m - 10) * 128 + k) * 128 + n];
    } else if (m == 14) {
        v = W1full[k * 128 + n];
    } else if (m == 15) {
        v = W1full[(256 + k) * 128 + n];
    } else if (m == 16) {
        v = W11full[k * 128 + n];
    } else {
        v = W11full[(256 + k) * 128 + n];
    }
    char* basep = (char*)g_Wb + (size_t)m * 34816;
    *(__half*)(basep + (uint32_t)k * 272u + (uint32_t)n * 2u) = __float2half_rn(v);
}

// ---------------------------------------------------------------------------
// Shared mma machinery: 64 rows x 128 cols, K=128, single-pass fp16.
// 8 warps = 2(M) x 4(N).
// ---------------------------------------------------------------------------
__device__ __forceinline__ void copyB_async(uint32_t dst, int mat) {
    const uint4* src = &g_Wb[(size_t)mat * 2176];
    #pragma unroll
    for (int i = 0; i < 9; i++) {
        int idx = threadIdx.x + 256*i;
        if (idx < 2176) cp16(dst + idx*16, src + idx);
    }
}

__device__ __forceinline__ void mma_layer64(uint32_t sb, int warpM, int warpN,
                                            int lane, float (&acc)[2][4][4]) {
    #pragma unroll
    for (int m = 0; m < 2; m++)
        #pragma unroll
        for (int j = 0; j < 4; j++)
            #pragma unroll
            for (int c = 0; c < 4; c++) acc[m][j][c] = 0.0f;

    uint32_t aA = sb + M_A + (uint32_t)(warpM*32 + (lane & 15))*AST
                + (uint32_t)(lane >> 4)*16;
    uint32_t bB = sb + M_B + (uint32_t)(lane & 15)*AST
                + (uint32_t)(warpN*4 + (lane >> 4))*16;

    #pragma unroll
    for (int ks = 0; ks < 8; ks++) {
        uint32_t ah0[4], ah1[4];
        ldm4(ah0, aA + ks*32);
        ldm4(ah1, aA + ks*32 + 16*AST);
        #pragma unroll
        for (int ng = 0; ng < 2; ng++) {
            uint32_t bh[4];
            ldm4t(bh, bB + ks*16*AST + ng*32);
            mma_f16(acc[0][2*ng],   ah0, bh[0], bh[1]);
            mma_f16(acc[1][2*ng],   ah1, bh[0], bh[1]);
            mma_f16(acc[0][2*ng+1], ah0, bh[2], bh[3]);
            mma_f16(acc[1][2*ng+1], ah1, bh[2], bh[3]);
        }
    }
}

// load 64 fp32 rows -> fp16 into smem
__device__ __forceinline__ void loadA64(char* sm, const float* src, int tid) {
    for (int idx = tid; idx < 64*64; idx += 256) {
        int r = idx >> 6, cp = idx & 63;
        float2 x = *(const float2*)&src[(size_t)r*NH + cp*2];
        *(uint32_t*)(sm + M_A + r*AST + cp*4) = pack_f16(x.x, x.y);
    }
}

// cp.async 64 fp16 rows from packed cache (row stride 64 uint32)
__device__ __forceinline__ void loadA64_cached(uint32_t sb, const uint32_t* cache,
                                               size_t row0, int tid) {
    #pragma unroll
    for (int i = 0; i < 4; i++) {
        int idx = tid + 256*i;          // 1024 x 16B
        int r = idx >> 4, q4 = (idx & 15) * 4;
        cp16(sb + M_A + r*AST + q4*4, &cache[(row0 + r)*64 + q4]);
    }
}

// ---------------------------------------------------------------------------
// tokenPG fused: P = A@W14 + b ; G = A@W15 (fp16 packed out). grid 64.
// ---------------------------------------------------------------------------
__global__ void __launch_bounds__(256, 3) tokenPG_kernel(
    const float* __restrict__ A, const float* __restrict__ bias,
    uint32_t* __restrict__ P, uint32_t* __restrict__ G)
{
    extern __shared__ char sm[];
    uint32_t sb = smem_u32(sm);
    int tid = threadIdx.x;
    int wid = tid >> 5, lane = tid & 31;
    int warpM = wid & 1, warpN = wid >> 1;
    int qr = lane >> 2, qc = lane & 3;
    int bl0 = blockIdx.x * 64;
    int cBase = warpN*32 + 2*qc;

    copyB_async(sb + M_B, 14);
    CP_COMMIT();
    loadA64(sm, A + (size_t)bl0*NH, tid);
    CP_WAIT0();
    __syncthreads();

    float acc[2][4][4];
    mma_layer64(sb, warpM, warpN, lane, acc);
    __syncthreads();
    copyB_async(sb + M_B, 15);
    CP_COMMIT();

    #pragma unroll
    for (int mf = 0; mf < 2; mf++)
        #pragma unroll
        for (int j = 0; j < 4; j++) {
            int C = cBase + j*8;
            float2 bv = *(const float2*)&bias[C];
            #pragma unroll
            for (int h = 0; h < 2; h++) {
                int R = warpM*32 + mf*16 + h*8 + qr;
                P[(size_t)(bl0 + R)*64 + (C >> 1)] =
                    pack_f16(acc[mf][j][2*h+0] + bv.x, acc[mf][j][2*h+1] + bv.y);
            }
        }
    CP_WAIT0();
    __syncthreads();

    mma_layer64(sb, warpM, warpN, lane, acc);
    #pragma unroll
    for (int mf = 0; mf < 2; mf++)
        #pragma unroll
        for (int j = 0; j < 4; j++) {
            int C = cBase + j*8;
            #pragma unroll
            for (int h = 0; h < 2; h++) {
                int R = warpM*32 + mf*16 + h*8 + qr;
                G[(size_t)(bl0 + R)*64 + (C >> 1)] =
                    pack_f16(acc[mf][j][2*h+0], acc[mf][j][2*h+1]);
            }
        }
}

// ---------------------------------------------------------------------------
// mlp3: 64 edge rows per CTA. MODE 0 = node (2 layers + masked Z row-sum;
// also writes hE fp16 cache). MODE 1 = edge (3 layers + residual + LN3;
// A built from fp16 cache via cp.async). P/G are fp16-packed.
// ---------------------------------------------------------------------------
template<int MODE>
__global__ void __launch_bounds__(256, 3) mlp3_kernel(
    const float* __restrict__ hE,
    const uint32_t* __restrict__ P, const uint32_t* __restrict__ G,
    const float* __restrict__ bias2, const float* __restrict__ bias3,
    const float* __restrict__ mask_attend,
    const float* __restrict__ ln3s, const float* __restrict__ ln3b,
    float* __restrict__ out_hE, int matBase)
{
    extern __shared__ char sm[];
    uint32_t sb = smem_u32(sm);

    int tid = threadIdx.x;
    int wid = tid >> 5, lane = tid & 31;
    int warpM = wid & 1, warpN = wid >> 1;
    int qr = lane >> 2, qc = lane & 3;
    int e0 = blockIdx.x * 64;
    int cBase = warpN*32 + 2*qc;

    int Row[2][2];
    #pragma unroll
    for (int mf = 0; mf < 2; mf++)
        #pragma unroll
        for (int h = 0; h < 2; h++)
            Row[mf][h] = warpM*32 + mf*16 + h*8 + qr;

    copyB_async(sb + M_B, matBase + 0);
    if (MODE == 0) {
        CP_COMMIT();
        // convert hE -> fp16 smem + write cache
        for (int idx = tid; idx < 64*64; idx += 256) {
            int r = idx >> 6, cp = idx & 63;
            float2 x = *(const float2*)&hE[(size_t)(e0 + r)*NH + cp*2];
            uint32_t u = pack_f16(x.x, x.y);
            *(uint32_t*)(sm + M_A + r*AST + cp*4) = u;
            g_hEf16[(size_t)(e0 + r)*64 + cp] = u;
        }
    } else {
        loadA64_cached(sb, g_hEf16, (size_t)e0, tid);
        CP_COMMIT();
    }
    // L2 prefetch of P/G gather rows for epilogue 1
    {
        int r = tid >> 2, ln = tid & 3;
        int e = e0 + r;
        int tok = e / 48;
        int batch = (e >= NL*NK) ? 1 : 0;
        PREF_L2(&P[(size_t)tok*64 + ln*16]);
        PREF_L2(&G[(size_t)(batch*NL + g_idx32[e])*64 + ln*16]);
    }
    CP_WAIT0();
    __syncthreads();

    float acc[2][4][4];

    // ---- layer 1 ----
    mma_layer64(sb, warpM, warpN, lane, acc);
    __syncthreads();
    copyB_async(sb + M_B, matBase + 1);
    CP_COMMIT();
    {
        const uint32_t* Pr[2][2];
        const uint32_t* Gr[2][2];
        #pragma unroll
        for (int mf = 0; mf < 2; mf++)
            #pragma unroll
            for (int h = 0; h < 2; h++) {
                int e = e0 + Row[mf][h];
                int tok = e / 48;
                int batch = (e >= NL*NK) ? 1 : 0;
                Pr[mf][h] = P + (size_t)tok * 64;
                Gr[mf][h] = G + (size_t)(batch*NL + g_idx32[e]) * 64;
            }
        #pragma unroll
        for (int mf = 0; mf < 2; mf++)
            #pragma unroll
            for (int j = 0; j < 4; j++) {
                int C = cBase + j*8;
                #pragma unroll
                for (int h = 0; h < 2; h++) {
                    float2 pv = unpack_f16(Pr[mf][h][C >> 1]);
                    float2 gv = unpack_f16(Gr[mf][h][C >> 1]);
                    float v0 = gelu_f(acc[mf][j][2*h+0] + pv.x + gv.x);
                    float v1 = gelu_f(acc[mf][j][2*h+1] + pv.y + gv.y);
                    int R = Row[mf][h];
                    *(uint32_t*)(sm + M_A + R*AST + C*2) = pack_f16(v0, v1);
                }
            }
    }
    CP_WAIT0();
    __syncthreads();

    // ---- layer 2 ----
    mma_layer64(sb, warpM, warpN, lane, acc);
    __syncthreads();

    if (MODE == 0) {
        // Z = gelu(acc + b2); stage Z*mask (fp32); per-token row-sum -> partials
        float* stage = (float*)(sm + M_A);  // [64][136] f32 (aliases A+B)
        #pragma unroll
        for (int mf = 0; mf < 2; mf++)
            #pragma unroll
            for (int h = 0; h < 2; h++) {
                int R = Row[mf][h];
                float mk = mask_attend[e0 + R];
                #pragma unroll
                for (int j = 0; j < 4; j++) {
                    int C = cBase + j*8;
                    float2 bv = *(const float2*)&bias2[C];
                    float2 o2;
                    o2.x = gelu_f(acc[mf][j][2*h+0] + bv.x) * mk;
                    o2.y = gelu_f(acc[mf][j][2*h+1] + bv.y) * mk;
                    *(float2*)&stage[R*136 + C] = o2;
                }
            }
        __syncthreads();
        int t0 = e0 / 48;
        int tend = (e0 + 63) / 48;
        for (int t = t0 + (tid >> 7); t <= tend; t += 2) {
            int col = tid & 127;
            int rs = max(t*48 - e0, 0), re = min(t*48 + 47 - e0, 63);
            float sacc = 0.0f;
            for (int rr = rs; rr <= re; rr++) sacc += stage[rr*136 + col];
            if (t*48 >= e0) g_partA[(size_t)t*NH + col] = sacc;
            else            g_partB[(size_t)t*NH + col] = sacc;
        }
        return;
    }

    // ---- edge path: layer-2 epilogue, layer 3, LN3 ----
    copyB_async(sb + M_B, matBase + 2);
    CP_COMMIT();
    #pragma unroll
    for (int mf = 0; mf < 2; mf++)
        #pragma unroll
        for (int j = 0; j < 4; j++) {
            int C = cBase + j*8;
            float2 bv = *(const float2*)&bias2[C];
            #pragma unroll
            for (int h = 0; h < 2; h++) {
                float v0 = gelu_f(acc[mf][j][2*h+0] + bv.x);
                float v1 = gelu_f(acc[mf][j][2*h+1] + bv.y);
                int R = Row[mf][h];
                *(uint32_t*)(sm + M_A + R*AST + C*2) = pack_f16(v0, v1);
            }
        }
    CP_WAIT0();
    __syncthreads();

    mma_layer64(sb, warpM, warpN, lane, acc);
    __syncthreads();

    float* stats = (float*)(sm + M_STAT);   // [4 warpN][64 rows][2]
    float s1[2][2], s2[2][2];
    #pragma unroll
    for (int mf = 0; mf < 2; mf++)
        #pragma unroll
        for (int h = 0; h < 2; h++) { s1[mf][h] = 0.f; s2[mf][h] = 0.f; }
    #pragma unroll
    for (int mf = 0; mf < 2; mf++)
        #pragma unroll
        for (int j = 0; j < 4; j++) {
            int C = cBase + j*8;
            float2 bv = *(const float2*)&bias3[C];
            #pragma unroll
            for (int h = 0; h < 2; h++) {
                int R = Row[mf][h];
                float2 he = *(const float2*)&hE[(size_t)(e0 + R)*NH + C];
                float v0 = acc[mf][j][2*h+0] + bv.x + he.x;
                float v1 = acc[mf][j][2*h+1] + bv.y + he.y;
                acc[mf][j][2*h+0] = v0;
                acc[mf][j][2*h+1] = v1;
                s1[mf][h] += v0 + v1;
                s2[mf][h] += v0*v0 + v1*v1;
            }
        }
    #pragma unroll
    for (int mf = 0; mf < 2; mf++)
        #pragma unroll
        for (int h = 0; h < 2; h++) {
            #pragma unroll
            for (int o = 1; o < 4; o <<= 1) {
                s1[mf][h] += __shfl_xor_sync(0xffffffffu, s1[mf][h], o);
                s2[mf][h] += __shfl_xor_sync(0xffffffffu, s2[mf][h], o);
            }
            if (qc == 0) {
                stats[(warpN*64 + Row[mf][h])*2 + 0] = s1[mf][h];
                stats[(warpN*64 + Row[mf][h])*2 + 1] = s2[mf][h];
            }
        }
    __syncthreads();
    #pragma unroll
    for (int mf = 0; mf < 2; mf++)
        #pragma unroll
        for (int h = 0; h < 2; h++) {
            int R = Row[mf][h];
            float S1 = 0.f, S2 = 0.f;
            #pragma unroll
            for (int g = 0; g < 4; g++) {
                S1 += stats[(g*64 + R)*2 + 0];
                S2 += stats[(g*64 + R)*2 + 1];
            }
            float mu = S1 * (1.0f / NH);
            float var = S2 * (1.0f / NH) - mu * mu;
            float rinv = rsqrtf(var + 1e-5f);
            #pragma unroll
            for (int j = 0; j < 4; j++) {
                int C = cBase + j*8;
                float2 gs = *(const float2*)&ln3s[C];
                float2 gb = *(const float2*)&ln3b[C];
                float2 o2;
                o2.x = (acc[mf][j][2*h+0] - mu) * rinv * gs.x + gb.x;
                o2.y = (acc[mf][j][2*h+1] - mu) * rinv * gs.y + gb.y;
                *(float2*)&out_hE[(size_t)(e0 + R)*NH + C] = o2;
            }
        }
}

// ---------------------------------------------------------------------------
// nodeFin: dh = S@W3 + (Σmask)*b3 ; h1 = LN1(hV + dh/30). 64 tokens/CTA.
// Writes g_h1 (fp32) and g_h1f16 (packed) for ffn1.
// ---------------------------------------------------------------------------
__global__ void __launch_bounds__(256) nodeFin_kernel(
    const float* __restrict__ hV, const float* __restrict__ b3,
    const float* __restrict__ mask_attend,
    const float* __restrict__ ln1s, const float* __restrict__ ln1b)
{
    extern __shared__ char sm[];
    uint32_t sb = smem_u32(sm);
    int tid = threadIdx.x;
    int wid = tid >> 5, lane = tid & 31;
    int warpM = wid & 1, warpN = wid >> 1;
    int qr = lane >> 2, qc = lane & 3;
    int bl0 = blockIdx.x * 64;
    int cBase = warpN*32 + 2*qc;

    copyB_async(sb + M_B, 2);   // W3
    CP_COMMIT();
    for (int idx = tid; idx < 64*64; idx += 256) {
        int r = idx >> 6, cp = idx & 63;
        int t = bl0 + r;
        float2 x = *(const float2*)&g_partA[(size_t)t*NH + cp*2];
        int s0 = t * 48;
        if (s0 / 64 != (s0 + 47) / 64) {
            float2 y = *(const float2*)&g_partB[(size_t)t*NH + cp*2];
            x.x += y.x; x.y += y.y;
        }
        *(uint32_t*)(sm + M_A + r*AST + cp*4) = pack_f16(x.x, x.y);
    }
    CP_WAIT0();
    __syncthreads();

    float acc[2][4][4];
    mma_layer64(sb, warpM, warpN, lane, acc);

    float* stats = (float*)(sm + M_STAT);
    float* msum  = (float*)(sm + M_STAT + 2048);
    if (tid < 64) {
        int t = bl0 + tid;
        float s = 0.0f;
        #pragma unroll 4
        for (int k = 0; k < NK; k += 4) {
            float4 m4 = *(const float4*)&mask_attend[t*NK + k];
            s += m4.x + m4.y + m4.z + m4.w;
        }
        msum[tid] = s;
    }
    __syncthreads();

    int Row[2][2];
    #pragma unroll
    for (int mf = 0; mf < 2; mf++)
        #pragma unroll
        for (int h = 0; h < 2; h++)
            Row[mf][h] = warpM*32 + mf*16 + h*8 + qr;

    float s1[2][2], s2[2][2];
    #pragma unroll
    for (int mf = 0; mf < 2; mf++)
        #pragma unroll
        for (int h = 0; h < 2; h++) { s1[mf][h] = 0.f; s2[mf][h] = 0.f; }

    #pragma unroll
    for (int mf = 0; mf < 2; mf++)
        #pragma unroll
        for (int j = 0; j < 4; j++) {
            int C = cBase + j*8;
            float2 bv = *(const float2*)&b3[C];
            #pragma unroll
            for (int h = 0; h < 2; h++) {
                int R = Row[mf][h];
                int t = bl0 + R;
                float ms = msum[R];
                float2 hv = *(const float2*)&hV[(size_t)t*NH + C];
                float v0 = hv.x + (acc[mf][j][2*h+0] + ms*bv.x) * (1.0f/30.0f);
                float v1 = hv.y + (acc[mf][j][2*h+1] + ms*bv.y) * (1.0f/30.0f);
                acc[mf][j][2*h+0] = v0;
                acc[mf][j][2*h+1] = v1;
                s1[mf][h] += v0 + v1;
                s2[mf][h] += v0*v0 + v1*v1;
            }
        }
    #pragma unroll
    for (int mf = 0; mf < 2; mf++)
        #pragma unroll
        for (int h = 0; h < 2; h++) {
            #pragma unroll
            for (int o = 1; o < 4; o <<= 1) {
                s1[mf][h] += __shfl_xor_sync(0xffffffffu, s1[mf][h], o);
                s2[mf][h] += __shfl_xor_sync(0xffffffffu, s2[mf][h], o);
            }
            if (qc == 0) {
                stats[(warpN*64 + Row[mf][h])*2 + 0] = s1[mf][h];
                stats[(warpN*64 + Row[mf][h])*2 + 1] = s2[mf][h];
            }
        }
    __syncthreads();
    #pragma unroll
    for (int mf = 0; mf < 2; mf++)
        #pragma unroll
        for (int h = 0; h < 2; h++) {
            int R = Row[mf][h];
            float S1 = 0.f, S2 = 0.f;
            #pragma unroll
            for (int g = 0; g < 4; g++) {
                S1 += stats[(g*64 + R)*2 + 0];
                S2 += stats[(g*64 + R)*2 + 1];
            }
            float mu = S1 * (1.0f / NH);
            float var = S2 * (1.0f / NH) - mu * mu;
            float rinv = rsqrtf(var + 1e-5f);
            #pragma unroll
            for (int j = 0; j < 4; j++) {
                int C = cBase + j*8;
                float2 gs = *(const float2*)&ln1s[C];
                float2 gb = *(const float2*)&ln1b[C];
                float2 o2;
                o2.x = (acc[mf][j][2*h+0] - mu) * rinv * gs.x + gb.x;
                o2.y = (acc[mf][j][2*h+1] - mu) * rinv * gs.y + gb.y;
                *(float2*)&g_h1[(size_t)(bl0 + R)*NH + C] = o2;
                g_h1f16[(size_t)(bl0 + R)*64 + (C >> 1)] = pack_f16(o2.x, o2.y);
            }
        }
}

// ---------------------------------------------------------------------------
// ffn1 (mma): H[64tok x 512] = gelu(h1 @ Wi + bi), fp16 out. One CTA loops
// the 4 N-tiles (A staged once, B prefetched under epilogue). grid 64.
// ---------------------------------------------------------------------------
__global__ void __launch_bounds__(256, 3) ffn1_kernel(const float* __restrict__ bi)
{
    extern __shared__ char sm[];
    uint32_t sb = smem_u32(sm);
    int tid = threadIdx.x;
    int wid = tid >> 5, lane = tid & 31;
    int warpM = wid & 1, warpN = wid >> 1;
    int qr = lane >> 2, qc = lane & 3;
    int bl0 = blockIdx.x * 64;
    int cBase = warpN*32 + 2*qc;

    copyB_async(sb + M_B, 6);
    loadA64_cached(sb, g_h1f16, (size_t)bl0, tid);
    CP_COMMIT();
    CP_WAIT0();
    __syncthreads();

    for (int y = 0; y < 4; y++) {
        int nb = y * 128;
        float acc[2][4][4];
        mma_layer64(sb, warpM, warpN, lane, acc);
        __syncthreads();
        if (y < 3) {
            copyB_async(sb + M_B, 7 + y);
            CP_COMMIT();
        }
        #pragma unroll
        for (int mf = 0; mf < 2; mf++)
            #pragma unroll
            for (int j = 0; j < 4; j++) {
                int C = cBase + j*8;
                float2 bv = *(const float2*)&bi[nb + C];
                #pragma unroll
                for (int h = 0; h < 2; h++) {
                    int R = warpM*32 + mf*16 + h*8 + qr;
                    float v0 = gelu_f(acc[mf][j][2*h+0] + bv.x);
                    float v1 = gelu_f(acc[mf][j][2*h+1] + bv.y);
                    uint32_t gi = ((uint32_t)(bl0 + R)*FFH + nb + C) >> 1;
                    g_Hhi[gi] = pack_f16(v0, v1);
                }
            }
        if (y < 3) {
            CP_WAIT0();
            __syncthreads();
        }
    }
}

// ---------------------------------------------------------------------------
// ffn2 (mma): hV2 = LN2(h1 + H @ Wo + bo) * mask_V, then fused
// P2 = hV2@W11P + b11, G2 = hV2@W11G (fp16 packed). 32 tok/CTA, grid 128.
// ---------------------------------------------------------------------------
#define F2_A   0
#define F2_B   8704
#define F2_STAT 43520
#define SMEM_F2 45568

__device__ __forceinline__ void mma_32(uint32_t sb, int warpM, int warpN,
                                       int lane, float (&acc)[4][4]) {
    #pragma unroll
    for (int j = 0; j < 4; j++)
        #pragma unroll
        for (int c = 0; c < 4; c++) acc[j][c] = 0.0f;
    uint32_t aA = sb + F2_A + (uint32_t)(warpM*16 + (lane & 15))*AST
                + (uint32_t)(lane >> 4)*16;
    uint32_t bB = sb + F2_B + (uint32_t)(lane & 15)*AST
                + (uint32_t)(warpN*4 + (lane >> 4))*16;
    #pragma unroll
    for (int ks = 0; ks < 8; ks++) {
        uint32_t ah[4];
        ldm4(ah, aA + ks*32);
        #pragma unroll
        for (int ng = 0; ng < 2; ng++) {
            uint32_t bh[4];
            ldm4t(bh, bB + ks*16*AST + ng*32);
            mma_f16(acc[2*ng],   ah, bh[0], bh[1]);
            mma_f16(acc[2*ng+1], ah, bh[2], bh[3]);
        }
    }
}

__global__ void __launch_bounds__(256) ffn2_kernel(
    const float* __restrict__ bo,
    const float* __restrict__ ln2s, const float* __restrict__ ln2b,
    const float* __restrict__ mask_V, const float* __restrict__ b11,
    float* __restrict__ out_hV,
    uint32_t* __restrict__ P2, uint32_t* __restrict__ G2)
{
    extern __shared__ char sm[];
    uint32_t sb = smem_u32(sm);
    int tid = threadIdx.x;
    int wid = tid >> 5, lane = tid & 31;
    int warpM = wid & 1, warpN = wid >> 1;   // 2 x 4
    int qr = lane >> 2, qc = lane & 3;
    int bl0 = blockIdx.x * 32;
    int cBase = warpN*32 + 2*qc;

    float acc[4][4];
    #pragma unroll
    for (int j = 0; j < 4; j++)
        #pragma unroll
        for (int c = 0; c < 4; c++) acc[j][c] = 0.0f;

    for (int ch = 0; ch < 4; ch++) {
        {
            int idx = tid;
            #pragma unroll
            for (int i = 0; i < 2; i++) {
                int r = idx >> 4, q4 = (idx & 15) * 4;
                uint32_t gi = (uint32_t)(bl0 + r)*256 + ch*64 + q4;
                cp16(sb + F2_A + r*AST + q4*4, &g_Hhi[gi]);
                idx += 256;
            }
        }
        copyB_async(sb + F2_B, 10 + ch);
        CP_COMMIT();
        CP_WAIT0();
        __syncthreads();

        uint32_t aA = sb + F2_A + (uint32_t)(warpM*16 + (lane & 15))*AST
                    + (uint32_t)(lane >> 4)*16;
        uint32_t bB = sb + F2_B + (uint32_t)(lane & 15)*AST
                    + (uint32_t)(warpN*64 + (lane >> 4)*16);

        #pragma unroll
        for (int ks = 0; ks < 8; ks++) {
            uint32_t ah[4];
            ldm4(ah, aA + ks*32);
            #pragma unroll
            for (int ng = 0; ng < 2; ng++) {
                uint32_t bh[4];
                ldm4t(bh, bB + ks*16*AST + ng*32);
                mma_f16(acc[2*ng],   ah, bh[0], bh[1]);
                mma_f16(acc[2*ng+1], ah, bh[2], bh[3]);
            }
        }
        __syncthreads();
    }

    float* stats = (float*)(sm + F2_STAT);
    float s1[2], s2[2];
    #pragma unroll
    for (int h = 0; h < 2; h++) { s1[h] = 0.f; s2[h] = 0.f; }
    #pragma unroll
    for (int j = 0; j < 4; j++) {
        int C = cBase + j*8;
        float2 bv = *(const float2*)&bo[C];
        #pragma unroll
        for (int h = 0; h < 2; h++) {
            int R = warpM*16 + h*8 + qr;
            float2 hv = *(const float2*)&g_h1[(size_t)(bl0 + R)*NH + C];
            float v0 = acc[j][2*h+0] + bv.x + hv.x;
            float v1 = acc[j][2*h+1] + bv.y + hv.y;
            acc[j][2*h+0] = v0;
            acc[j][2*h+1] = v1;
            s1[h] += v0 + v1;
            s2[h] += v0*v0 + v1*v1;
        }
    }
    #pragma unroll
    for (int h = 0; h < 2; h++) {
        #pragma unroll
        for (int o = 1; o < 4; o <<= 1) {
            s1[h] += __shfl_xor_sync(0xffffffffu, s1[h], o);
            s2[h] += __shfl_xor_sync(0xffffffffu, s2[h], o);
        }
        if (qc == 0) {
            int R = warpM*16 + h*8 + qr;
            stats[(warpN*32 + R)*2 + 0] = s1[h];
            stats[(warpN*32 + R)*2 + 1] = s2[h];
        }
    }
    __syncthreads();
    #pragma unroll
    for (int h = 0; h < 2; h++) {
        int R = warpM*16 + h*8 + qr;
        float S1 = 0.f, S2 = 0.f;
        #pragma unroll
        for (int g = 0; g < 4; g++) {
            S1 += stats[(g*32 + R)*2 + 0];
            S2 += stats[(g*32 + R)*2 + 1];
        }
        float mu = S1 * (1.0f / NH);
        float var = S2 * (1.0f / NH) - mu * mu;
        float rinv = rsqrtf(var + 1e-5f);
        int token = bl0 + R;
        float mk = mask_V[token];
        #pragma unroll
        for (int j = 0; j < 4; j++) {
            int C = cBase + j*8;
            float2 gs = *(const float2*)&ln2s[C];
            float2 gb = *(const float2*)&ln2b[C];
            float2 o2;
            o2.x = ((acc[j][2*h+0] - mu) * rinv * gs.x + gb.x) * mk;
            o2.y = ((acc[j][2*h+1] - mu) * rinv * gs.y + gb.y) * mk;
            *(float2*)&out_hV[(size_t)token*NH + C] = o2;
            *(uint32_t*)(sm + F2_A + R*AST + C*2) = pack_f16(o2.x, o2.y);
        }
    }
    __syncthreads();

    // fused P2 = hV2 @ W11P + b11 (fp16 out)
    copyB_async(sb + F2_B, 16);
    CP_COMMIT();
    CP_WAIT0();
    __syncthreads();
    float acc2[4][4];
    mma_32(sb, warpM, warpN, lane, acc2);
    #pragma unroll
    for (int j = 0; j < 4; j++) {
        int C = cBase + j*8;
        float2 bv = *(const float2*)&b11[C];
        #pragma unroll
        for (int h = 0; h < 2; h++) {
            int R = warpM*16 + h*8 + qr;
            P2[(size_t)(bl0 + R)*64 + (C >> 1)] =
                pack_f16(acc2[j][2*h+0] + bv.x, acc2[j][2*h+1] + bv.y);
        }
    }
    __syncthreads();

    // fused G2 = hV2 @ W11G (fp16 out)
    copyB_async(sb + F2_B, 17);
    CP_COMMIT();
    CP_WAIT0();
    __syncthreads();
    mma_32(sb, warpM, warpN, lane, acc2);
    #pragma unroll
    for (int j = 0; j < 4; j++) {
        int C = cBase + j*8;
        #pragma unroll
        for (int h = 0; h < 2; h++) {
            int R = warpM*16 + h*8 + qr;
            G2[(size_t)(bl0 + R)*64 + (C >> 1)] =
                pack_f16(acc2[j][2*h+0], acc2[j][2*h+1]);
        }
    }
}

// ---------------------------------------------------------------------------

extern "C" void kernel_launch(void* const* d_in, const int* in_sizes, int n_in,
                              void* d_out, int out_size)
{
    const float* h_V         = (const float*)d_in[0];
    const float* h_E         = (const float*)d_in[1];
    const void*  E_idx       =               d_in[2];
    const float* mask_V      = (const float*)d_in[3];
    const float* mask_attend = (const float*)d_in[4];
    const float* W1  = (const float*)d_in[5],  *b1  = (const float*)d_in[6];
    const float* W2  = (const float*)d_in[7],  *b2  = (const float*)d_in[8];
    const float* W3  = (const float*)d_in[9],  *b3  = (const float*)d_in[10];
    const float* W11 = (const float*)d_in[11], *b11 = (const float*)d_in[12];
    const float* W12 = (const float*)d_in[13], *b12 = (const float*)d_in[14];
    const float* W13 = (const float*)d_in[15], *b13 = (const float*)d_in[16];
    const float* Wi  = (const float*)d_in[17], *bi  = (const float*)d_in[18];
    const float* Wo  = (const float*)d_in[19], *bo  = (const float*)d_in[20];
    const float* ln1s = (const float*)d_in[21], *ln1b = (const float*)d_in[22];
    const float* ln2s = (const float*)d_in[23], *ln2b = (const float*)d_in[24];
    const float* ln3s = (const float*)d_in[25], *ln3b = (const float*)d_in[26];
    float* out = (float*)d_out;

    uint32_t *pP1, *pG1, *pP2, *pG2;
    cudaGetSymbolAddress((void**)&pP1,  g_P1);
    cudaGetSymbolAddress((void**)&pG1,  g_G1);
    cudaGetSymbolAddress((void**)&pP2,  g_P2);
    cudaGetSymbolAddress((void**)&pG2,  g_G2);

    cudaFuncSetAttribute(tokenPG_kernel, cudaFuncAttributeMaxDynamicSharedMemorySize, SMEM64);
    cudaFuncSetAttribute(ffn1_kernel,  cudaFuncAttributeMaxDynamicSharedMemorySize, SMEM64);
    cudaFuncSetAttribute(ffn2_kernel,  cudaFuncAttributeMaxDynamicSharedMemorySize, SMEM_F2);
    cudaFuncSetAttribute(nodeFin_kernel, cudaFuncAttributeMaxDynamicSharedMemorySize, SMEMNF);
    cudaFuncSetAttribute(mlp3_kernel<0>, cudaFuncAttributeMaxDynamicSharedMemorySize, SMEM64);
    cudaFuncSetAttribute(mlp3_kernel<1>, cudaFuncAttributeMaxDynamicSharedMemorySize, SMEM64);

    convert_kernel<<<(NEDGE + 255) / 256, 256>>>(E_idx);

    wprep_kernel<<<(18*16384 + 255)/256, 256>>>(W1 + 128*NH, W2, W3,
                                                W11 + 128*NH, W12, W13, Wi, Wo,
                                                W1, W11);

    tokenPG_kernel<<<64, 256, SMEM64>>>(h_V, b1, pP1, pG1);

    mlp3_kernel<0><<<NEDGE/64, 256, SMEM64>>>(h_E, pP1, pG1, b2, nullptr,
                                              mask_attend, nullptr, nullptr,
                                              nullptr, 0);
    nodeFin_kernel<<<64, 256, SMEMNF>>>(h_V, b3, mask_attend, ln1s, ln1b);

    ffn1_kernel<<<64, 256, SMEM64>>>(bi);
    ffn2_kernel<<<128, 256, SMEM_F2>>>(bo, ln2s, ln2b, mask_V, b11,
                                       out, pP2, pG2);

    mlp3_kernel<1><<<NEDGE/64, 256, SMEM64>>>(h_E, pP2, pG2, b12, b13,
                                              nullptr, ln3s, ln3b,
                                              out + (size_t)NTOK * NH, 3);
}

// round 14
// speedup vs baseline: 1.0155x; 1.0155x over previous
#include <cuda_runtime.h>
#include <cuda_fp16.h>
#include <math.h>
#include <stdint.h>

#define NB 2
#define NL 2048
#define NK 48
#define NH 128
#define NTOK (NB*NL)
#define NEDGE (NB*NL*NK)
#define FFH 512

__device__ int   g_idx32[NEDGE];
__device__ float g_h1 [NTOK*NH];
__device__ uint32_t g_h1f16[NTOK*NH/2];
__device__ uint32_t g_hEf16[NEDGE*NH/2];
__device__ uint32_t g_Hhi[NTOK*FFH/2];
__device__ uint32_t g_P1 [NTOK*64];
__device__ uint32_t g_G1 [NTOK*64];
__device__ uint32_t g_P2 [NTOK*64];
__device__ uint32_t g_G2 [NTOK*64];
__device__ float g_partA[NTOK*NH];
__device__ float g_partB[NTOK*NH];
// 18 fp16 matrices [k][n] (128x128), rows padded to 272B -> 2176 uint4 each
// 0-2 node MLP, 3-5 edge MLP, 6-9 Wi col-tiles, 10-13 Wo k-chunks,
// 14 W1-P, 15 W1-G, 16 W11-P, 17 W11-G
__device__ uint4 g_Wb[18*2176];

#define AST 272
// 64-row tile layout (hi-only A)
#define M_A   0
#define M_B   17408
#define M_STAT 52224
#define SMEM64 54272
#define SMEMNF 54784

__device__ __forceinline__ float gelu_f(float x) {
    return 0.5f * x * (1.0f + erff(x * 0.7071067811865475f));
}

__device__ __forceinline__ uint32_t smem_u32(const void* p) {
    uint32_t a;
    asm("{ .reg .u64 t; cvta.to.shared.u64 t, %1; cvt.u32.u64 %0, t; }"
        : "=r"(a) : "l"(p));
    return a;
}

__device__ __forceinline__ uint32_t pack_f16(float v0, float v1) {
    __half2 h = __floats2half2_rn(v0, v1);
    return *(uint32_t*)&h;
}

__device__ __forceinline__ float2 unpack_f16(uint32_t u) {
    return __half22float2(*(__half2*)&u);
}

__device__ __forceinline__ void cp16(uint32_t dst, const void* src) {
    asm volatile("cp.async.cg.shared.global [%0], [%1], 16;"
        :: "r"(dst), "l"(src));
}
#define CP_COMMIT() asm volatile("cp.async.commit_group;" ::: "memory")
#define CP_WAIT0()  asm volatile("cp.async.wait_group 0;" ::: "memory")
#define PREF_L2(p)  asm volatile("prefetch.global.L2 [%0];" :: "l"(p))

__device__ __forceinline__ void ldm4(uint32_t r[4], uint32_t a) {
    asm volatile("ldmatrix.sync.aligned.m8n8.x4.shared.b16 {%0,%1,%2,%3}, [%4];"
        : "=r"(r[0]), "=r"(r[1]), "=r"(r[2]), "=r"(r[3]) : "r"(a));
}
__device__ __forceinline__ void ldm4t(uint32_t r[4], uint32_t a) {
    asm volatile("ldmatrix.sync.aligned.m8n8.x4.trans.shared.b16 {%0,%1,%2,%3}, [%4];"
        : "=r"(r[0]), "=r"(r[1]), "=r"(r[2]), "=r"(r[3]) : "r"(a));
}
__device__ __forceinline__ void mma_f16(float c[4], const uint32_t a[4],
                                        uint32_t b0, uint32_t b1) {
    asm volatile(
        "mma.sync.aligned.m16n8k16.row.col.f32.f16.f16.f32 "
        "{%0,%1,%2,%3}, {%4,%5,%6,%7}, {%8,%9}, {%0,%1,%2,%3};"
        : "+f"(c[0]), "+f"(c[1]), "+f"(c[2]), "+f"(c[3])
        : "r"(a[0]), "r"(a[1]), "r"(a[2]), "r"(a[3]), "r"(b0), "r"(b1));
}

// ---------------------------------------------------------------------------
// convert: dtype detect (per-block, redundant) + normalize E_idx to int32.
// ---------------------------------------------------------------------------
__global__ void convert_kernel(const void* __restrict__ e) {
    __shared__ int s_is64;
    if (threadIdx.x == 0) {
        const int* w = (const int*)e;
        int nz = 0;
        #pragma unroll 8
        for (int i = 1; i < 256; i += 2) nz |= (w[i] != 0);
        s_is64 = (nz == 0);
    }
    __syncthreads();
    int i = blockIdx.x * blockDim.x + threadIdx.x;
    if (i >= NEDGE) return;
    if (s_is64) g_idx32[i] = (int)((const long long*)e)[i];
    else        g_idx32[i] = ((const int*)e)[i];
}

// ---------------------------------------------------------------------------
// wprep: all weights -> fp16 tiles [k][n], rows padded to 272B.
// ---------------------------------------------------------------------------
__global__ void wprep_kernel(const float* W0, const float* W1, const float* W2,
                             const float* W3, const float* W4, const float* W5,
                             const float* Wi, const float* Wo,
                             const float* W1full, const float* W11full) {
    int gid = blockIdx.x * 256 + threadIdx.x;
    if (gid >= 18 * 16384) return;
    int m = gid >> 14, rem = gid & 16383;
    int k = rem >> 7, n = rem & 127;
    float v;
    if (m < 6) {
        const float* W = (m == 0) ? W0 : (m == 1) ? W1 : (m == 2) ? W2
                       : (m == 3) ? W3 : (m == 4) ? W4 : W5;
        v = W[k * 128 + n];
    } else if (m < 10) {
        v = Wi[k * FFH + (m - 6) * 128 + n];
    } else if (m < 14) {
        v = Wo[((m - 10) * 128 + k) * 128 + n];
    } else if (m == 14) {
        v = W1full[k * 128 + n];
    } else if (m == 15) {
        v = W1full[(256 + k) * 128 + n];
    } else if (m == 16) {
        v = W11full[k * 128 + n];
    } else {
        v = W11full[(256 + k) * 128 + n];
    }
    char* basep = (char*)g_Wb + (size_t)m * 34816;
    *(__half*)(basep + (uint32_t)k * 272u + (uint32_t)n * 2u) = __float2half_rn(v);
}

// ---------------------------------------------------------------------------
// Shared mma machinery: 64 rows x 128 cols, K=128, single-pass fp16.
// 8 warps = 2(M) x 4(N).
// ---------------------------------------------------------------------------
__device__ __forceinline__ void copyB_async(uint32_t dst, int mat) {
    const uint4* src = &g_Wb[(size_t)mat * 2176];
    #pragma unroll
    for (int i = 0; i < 9; i++) {
        int idx = threadIdx.x + 256*i;
        if (idx < 2176) cp16(dst + idx*16, src + idx);
    }
}

__device__ __forceinline__ void mma_layer64(uint32_t sb, int warpM, int warpN,
                                            int lane, float (&acc)[2][4][4]) {
    #pragma unroll
    for (int m = 0; m < 2; m++)
        #pragma unroll
        for (int j = 0; j < 4; j++)
            #pragma unroll
            for (int c = 0; c < 4; c++) acc[m][j][c] = 0.0f;

    uint32_t aA = sb + M_A + (uint32_t)(warpM*32 + (lane & 15))*AST
                + (uint32_t)(lane >> 4)*16;
    uint32_t bB = sb + M_B + (uint32_t)(lane & 15)*AST
                + (uint32_t)(warpN*4 + (lane >> 4))*16;

    #pragma unroll
    for (int ks = 0; ks < 8; ks++) {
        uint32_t ah0[4], ah1[4];
        ldm4(ah0, aA + ks*32);
        ldm4(ah1, aA + ks*32 + 16*AST);
        #pragma unroll
        for (int ng = 0; ng < 2; ng++) {
            uint32_t bh[4];
            ldm4t(bh, bB + ks*16*AST + ng*32);
            mma_f16(acc[0][2*ng],   ah0, bh[0], bh[1]);
            mma_f16(acc[1][2*ng],   ah1, bh[0], bh[1]);
            mma_f16(acc[0][2*ng+1], ah0, bh[2], bh[3]);
            mma_f16(acc[1][2*ng+1], ah1, bh[2], bh[3]);
        }
    }
}

// load 64 fp32 rows -> fp16 into smem
__device__ __forceinline__ void loadA64(char* sm, const float* src, int tid) {
    for (int idx = tid; idx < 64*64; idx += 256) {
        int r = idx >> 6, cp = idx & 63;
        float2 x = *(const float2*)&src[(size_t)r*NH + cp*2];
        *(uint32_t*)(sm + M_A + r*AST + cp*4) = pack_f16(x.x, x.y);
    }
}

// cp.async 64 fp16 rows from packed cache (row stride 64 uint32)
__device__ __forceinline__ void loadA64_cached(uint32_t sb, const uint32_t* cache,
                                               size_t row0, int tid) {
    #pragma unroll
    for (int i = 0; i < 4; i++) {
        int idx = tid + 256*i;          // 1024 x 16B
        int r = idx >> 4, q4 = (idx & 15) * 4;
        cp16(sb + M_A + r*AST + q4*4, &cache[(row0 + r)*64 + q4]);
    }
}

// ---------------------------------------------------------------------------
// tokenPG fused: P = A@W14 + b ; G = A@W15 (fp16 packed out). grid 64.
// ---------------------------------------------------------------------------
__global__ void __launch_bounds__(256, 3) tokenPG_kernel(
    const float* __restrict__ A, const float* __restrict__ bias,
    uint32_t* __restrict__ P, uint32_t* __restrict__ G)
{
    extern __shared__ char sm[];
    uint32_t sb = smem_u32(sm);
    int tid = threadIdx.x;
    int wid = tid >> 5, lane = tid & 31;
    int warpM = wid & 1, warpN = wid >> 1;
    int qr = lane >> 2, qc = lane & 3;
    int bl0 = blockIdx.x * 64;
    int cBase = warpN*32 + 2*qc;

    copyB_async(sb + M_B, 14);
    CP_COMMIT();
    loadA64(sm, A + (size_t)bl0*NH, tid);
    CP_WAIT0();
    __syncthreads();

    float acc[2][4][4];
    mma_layer64(sb, warpM, warpN, lane, acc);
    __syncthreads();
    copyB_async(sb + M_B, 15);
    CP_COMMIT();

    #pragma unroll
    for (int mf = 0; mf < 2; mf++)
        #pragma unroll
        for (int j = 0; j < 4; j++) {
            int C = cBase + j*8;
            float2 bv = *(const float2*)&bias[C];
            #pragma unroll
            for (int h = 0; h < 2; h++) {
                int R = warpM*32 + mf*16 + h*8 + qr;
                P[(size_t)(bl0 + R)*64 + (C >> 1)] =
                    pack_f16(acc[mf][j][2*h+0] + bv.x, acc[mf][j][2*h+1] + bv.y);
            }
        }
    CP_WAIT0();
    __syncthreads();

    mma_layer64(sb, warpM, warpN, lane, acc);
    #pragma unroll
    for (int mf = 0; mf < 2; mf++)
        #pragma unroll
        for (int j = 0; j < 4; j++) {
            int C = cBase + j*8;
            #pragma unroll
            for (int h = 0; h < 2; h++) {
                int R = warpM*32 + mf*16 + h*8 + qr;
                G[(size_t)(bl0 + R)*64 + (C >> 1)] =
                    pack_f16(acc[mf][j][2*h+0], acc[mf][j][2*h+1]);
            }
        }
}

// ---------------------------------------------------------------------------
// mlp3: 64 edge rows per CTA. MODE 0 = node (2 layers + masked Z row-sum;
// also writes hE fp16 cache). MODE 1 = edge (3 layers + residual + LN3;
// A built from fp16 cache via cp.async). P/G are fp16-packed.
// ---------------------------------------------------------------------------
template<int MODE>
__global__ void __launch_bounds__(256, 3) mlp3_kernel(
    const float* __restrict__ hE,
    const uint32_t* __restrict__ P, const uint32_t* __restrict__ G,
    const float* __restrict__ bias2, const float* __restrict__ bias3,
    const float* __restrict__ mask_attend,
    const float* __restrict__ ln3s, const float* __restrict__ ln3b,
    float* __restrict__ out_hE, int matBase)
{
    extern __shared__ char sm[];
    uint32_t sb = smem_u32(sm);

    int tid = threadIdx.x;
    int wid = tid >> 5, lane = tid & 31;
    int warpM = wid & 1, warpN = wid >> 1;
    int qr = lane >> 2, qc = lane & 3;
    int e0 = blockIdx.x * 64;
    int cBase = warpN*32 + 2*qc;

    int Row[2][2];
    #pragma unroll
    for (int mf = 0; mf < 2; mf++)
        #pragma unroll
        for (int h = 0; h < 2; h++)
            Row[mf][h] = warpM*32 + mf*16 + h*8 + qr;

    copyB_async(sb + M_B, matBase + 0);
    if (MODE == 0) {
        CP_COMMIT();
        // convert hE -> fp16 smem + write cache
        for (int idx = tid; idx < 64*64; idx += 256) {
            int r = idx >> 6, cp = idx & 63;
            float2 x = *(const float2*)&hE[(size_t)(e0 + r)*NH + cp*2];
            uint32_t u = pack_f16(x.x, x.y);
            *(uint32_t*)(sm + M_A + r*AST + cp*4) = u;
            g_hEf16[(size_t)(e0 + r)*64 + cp] = u;
        }
    } else {
        loadA64_cached(sb, g_hEf16, (size_t)e0, tid);
        CP_COMMIT();
    }
    // L2 prefetch of P/G gather rows for epilogue 1
    {
        int r = tid >> 2, ln = tid & 3;
        int e = e0 + r;
        int tok = e / 48;
        int batch = (e >= NL*NK) ? 1 : 0;
        PREF_L2(&P[(size_t)tok*64 + ln*16]);
        PREF_L2(&G[(size_t)(batch*NL + g_idx32[e])*64 + ln*16]);
    }
    CP_WAIT0();
    __syncthreads();

    float acc[2][4][4];

    // ---- layer 1 ----
    mma_layer64(sb, warpM, warpN, lane, acc);
    __syncthreads();
    copyB_async(sb + M_B, matBase + 1);
    CP_COMMIT();
    {
        const uint32_t* Pr[2][2];
        const uint32_t* Gr[2][2];
        #pragma unroll
        for (int mf = 0; mf < 2; mf++)
            #pragma unroll
            for (int h = 0; h < 2; h++) {
                int e = e0 + Row[mf][h];
                int tok = e / 48;
                int batch = (e >= NL*NK) ? 1 : 0;
                Pr[mf][h] = P + (size_t)tok * 64;
                Gr[mf][h] = G + (size_t)(batch*NL + g_idx32[e]) * 64;
            }
        #pragma unroll
        for (int mf = 0; mf < 2; mf++)
            #pragma unroll
            for (int j = 0; j < 4; j++) {
                int C = cBase + j*8;
                #pragma unroll
                for (int h = 0; h < 2; h++) {
                    float2 pv = unpack_f16(Pr[mf][h][C >> 1]);
                    float2 gv = unpack_f16(Gr[mf][h][C >> 1]);
                    float v0 = gelu_f(acc[mf][j][2*h+0] + pv.x + gv.x);
                    float v1 = gelu_f(acc[mf][j][2*h+1] + pv.y + gv.y);
                    int R = Row[mf][h];
                    *(uint32_t*)(sm + M_A + R*AST + C*2) = pack_f16(v0, v1);
                }
            }
    }
    CP_WAIT0();
    __syncthreads();

    // ---- layer 2 ----
    mma_layer64(sb, warpM, warpN, lane, acc);
    __syncthreads();

    if (MODE == 0) {
        // Z = gelu(acc + b2); stage Z*mask (fp32); per-token row-sum -> partials
        float* stage = (float*)(sm + M_A);  // [64][136] f32 (aliases A+B)
        #pragma unroll
        for (int mf = 0; mf < 2; mf++)
            #pragma unroll
            for (int h = 0; h < 2; h++) {
                int R = Row[mf][h];
                float mk = mask_attend[e0 + R];
                #pragma unroll
                for (int j = 0; j < 4; j++) {
                    int C = cBase + j*8;
                    float2 bv = *(const float2*)&bias2[C];
                    float2 o2;
                    o2.x = gelu_f(acc[mf][j][2*h+0] + bv.x) * mk;
                    o2.y = gelu_f(acc[mf][j][2*h+1] + bv.y) * mk;
                    *(float2*)&stage[R*136 + C] = o2;
                }
            }
        __syncthreads();
        int t0 = e0 / 48;
        int tend = (e0 + 63) / 48;
        for (int t = t0 + (tid >> 7); t <= tend; t += 2) {
            int col = tid & 127;
            int rs = max(t*48 - e0, 0), re = min(t*48 + 47 - e0, 63);
            float sacc = 0.0f;
            for (int rr = rs; rr <= re; rr++) sacc += stage[rr*136 + col];
            if (t*48 >= e0) g_partA[(size_t)t*NH + col] = sacc;
            else            g_partB[(size_t)t*NH + col] = sacc;
        }
        return;
    }

    // ---- edge path: layer-2 epilogue, layer 3, LN3 ----
    copyB_async(sb + M_B, matBase + 2);
    CP_COMMIT();
    #pragma unroll
    for (int mf = 0; mf < 2; mf++)
        #pragma unroll
        for (int j = 0; j < 4; j++) {
            int C = cBase + j*8;
            float2 bv = *(const float2*)&bias2[C];
            #pragma unroll
            for (int h = 0; h < 2; h++) {
                float v0 = gelu_f(acc[mf][j][2*h+0] + bv.x);
                float v1 = gelu_f(acc[mf][j][2*h+1] + bv.y);
                int R = Row[mf][h];
                *(uint32_t*)(sm + M_A + R*AST + C*2) = pack_f16(v0, v1);
            }
        }
    CP_WAIT0();
    __syncthreads();

    mma_layer64(sb, warpM, warpN, lane, acc);
    __syncthreads();

    float* stats = (float*)(sm + M_STAT);   // [4 warpN][64 rows][2]
    float s1[2][2], s2[2][2];
    #pragma unroll
    for (int mf = 0; mf < 2; mf++)
        #pragma unroll
        for (int h = 0; h < 2; h++) { s1[mf][h] = 0.f; s2[mf][h] = 0.f; }
    #pragma unroll
    for (int mf = 0; mf < 2; mf++)
        #pragma unroll
        for (int j = 0; j < 4; j++) {
            int C = cBase + j*8;
            float2 bv = *(const float2*)&bias3[C];
            #pragma unroll
            for (int h = 0; h < 2; h++) {
                int R = Row[mf][h];
                float2 he = *(const float2*)&hE[(size_t)(e0 + R)*NH + C];
                float v0 = acc[mf][j][2*h+0] + bv.x + he.x;
                float v1 = acc[mf][j][2*h+1] + bv.y + he.y;
                acc[mf][j][2*h+0] = v0;
                acc[mf][j][2*h+1] = v1;
                s1[mf][h] += v0 + v1;
                s2[mf][h] += v0*v0 + v1*v1;
            }
        }
    #pragma unroll
    for (int mf = 0; mf < 2; mf++)
        #pragma unroll
        for (int h = 0; h < 2; h++) {
            #pragma unroll
            for (int o = 1; o < 4; o <<= 1) {
                s1[mf][h] += __shfl_xor_sync(0xffffffffu, s1[mf][h], o);
                s2[mf][h] += __shfl_xor_sync(0xffffffffu, s2[mf][h], o);
            }
            if (qc == 0) {
                stats[(warpN*64 + Row[mf][h])*2 + 0] = s1[mf][h];
                stats[(warpN*64 + Row[mf][h])*2 + 1] = s2[mf][h];
            }
        }
    __syncthreads();
    #pragma unroll
    for (int mf = 0; mf < 2; mf++)
        #pragma unroll
        for (int h = 0; h < 2; h++) {
            int R = Row[mf][h];
            float S1 = 0.f, S2 = 0.f;
            #pragma unroll
            for (int g = 0; g < 4; g++) {
                S1 += stats[(g*64 + R)*2 + 0];
                S2 += stats[(g*64 + R)*2 + 1];
            }
            float mu = S1 * (1.0f / NH);
            float var = S2 * (1.0f / NH) - mu * mu;
            float rinv = rsqrtf(var + 1e-5f);
            #pragma unroll
            for (int j = 0; j < 4; j++) {
                int C = cBase + j*8;
                float2 gs = *(const float2*)&ln3s[C];
                float2 gb = *(const float2*)&ln3b[C];
                float2 o2;
                o2.x = (acc[mf][j][2*h+0] - mu) * rinv * gs.x + gb.x;
                o2.y = (acc[mf][j][2*h+1] - mu) * rinv * gs.y + gb.y;
                *(float2*)&out_hE[(size_t)(e0 + R)*NH + C] = o2;
            }
        }
}

// ---------------------------------------------------------------------------
// nodeFin: dh = S@W3 + (Σmask)*b3 ; h1 = LN1(hV + dh/30). 64 tokens/CTA.
// Writes g_h1 (fp32) and g_h1f16 (packed) for ffn1.
// ---------------------------------------------------------------------------
__global__ void __launch_bounds__(256) nodeFin_kernel(
    const float* __restrict__ hV, const float* __restrict__ b3,
    const float* __restrict__ mask_attend,
    const float* __restrict__ ln1s, const float* __restrict__ ln1b)
{
    extern __shared__ char sm[];
    uint32_t sb = smem_u32(sm);
    int tid = threadIdx.x;
    int wid = tid >> 5, lane = tid & 31;
    int warpM = wid & 1, warpN = wid >> 1;
    int qr = lane >> 2, qc = lane & 3;
    int bl0 = blockIdx.x * 64;
    int cBase = warpN*32 + 2*qc;

    copyB_async(sb + M_B, 2);   // W3
    CP_COMMIT();
    for (int idx = tid; idx < 64*64; idx += 256) {
        int r = idx >> 6, cp = idx & 63;
        int t = bl0 + r;
        float2 x = *(const float2*)&g_partA[(size_t)t*NH + cp*2];
        int s0 = t * 48;
        if (s0 / 64 != (s0 + 47) / 64) {
            float2 y = *(const float2*)&g_partB[(size_t)t*NH + cp*2];
            x.x += y.x; x.y += y.y;
        }
        *(uint32_t*)(sm + M_A + r*AST + cp*4) = pack_f16(x.x, x.y);
    }
    CP_WAIT0();
    __syncthreads();

    float acc[2][4][4];
    mma_layer64(sb, warpM, warpN, lane, acc);

    float* stats = (float*)(sm + M_STAT);
    float* msum  = (float*)(sm + M_STAT + 2048);
    if (tid < 64) {
        int t = bl0 + tid;
        float s = 0.0f;
        #pragma unroll 4
        for (int k = 0; k < NK; k += 4) {
            float4 m4 = *(const float4*)&mask_attend[t*NK + k];
            s += m4.x + m4.y + m4.z + m4.w;
        }
        msum[tid] = s;
    }
    __syncthreads();

    int Row[2][2];
    #pragma unroll
    for (int mf = 0; mf < 2; mf++)
        #pragma unroll
        for (int h = 0; h < 2; h++)
            Row[mf][h] = warpM*32 + mf*16 + h*8 + qr;

    float s1[2][2], s2[2][2];
    #pragma unroll
    for (int mf = 0; mf < 2; mf++)
        #pragma unroll
        for (int h = 0; h < 2; h++) { s1[mf][h] = 0.f; s2[mf][h] = 0.f; }

    #pragma unroll
    for (int mf = 0; mf < 2; mf++)
        #pragma unroll
        for (int j = 0; j < 4; j++) {
            int C = cBase + j*8;
            float2 bv = *(const float2*)&b3[C];
            #pragma unroll
            for (int h = 0; h < 2; h++) {
                int R = Row[mf][h];
                int t = bl0 + R;
                float ms = msum[R];
                float2 hv = *(const float2*)&hV[(size_t)t*NH + C];
                float v0 = hv.x + (acc[mf][j][2*h+0] + ms*bv.x) * (1.0f/30.0f);
                float v1 = hv.y + (acc[mf][j][2*h+1] + ms*bv.y) * (1.0f/30.0f);
                acc[mf][j][2*h+0] = v0;
                acc[mf][j][2*h+1] = v1;
                s1[mf][h] += v0 + v1;
                s2[mf][h] += v0*v0 + v1*v1;
            }
        }
    #pragma unroll
    for (int mf = 0; mf < 2; mf++)
        #pragma unroll
        for (int h = 0; h < 2; h++) {
            #pragma unroll
            for (int o = 1; o < 4; o <<= 1) {
                s1[mf][h] += __shfl_xor_sync(0xffffffffu, s1[mf][h], o);
                s2[mf][h] += __shfl_xor_sync(0xffffffffu, s2[mf][h], o);
            }
            if (qc == 0) {
                stats[(warpN*64 + Row[mf][h])*2 + 0] = s1[mf][h];
                stats[(warpN*64 + Row[mf][h])*2 + 1] = s2[mf][h];
            }
        }
    __syncthreads();
    #pragma unroll
    for (int mf = 0; mf < 2; mf++)
        #pragma unroll
        for (int h = 0; h < 2; h++) {
            int R = Row[mf][h];
            float S1 = 0.f, S2 = 0.f;
            #pragma unroll
            for (int g = 0; g < 4; g++) {
                S1 += stats[(g*64 + R)*2 + 0];
                S2 += stats[(g*64 + R)*2 + 1];
            }
            float mu = S1 * (1.0f / NH);
            float var = S2 * (1.0f / NH) - mu * mu;
            float rinv = rsqrtf(var + 1e-5f);
            #pragma unroll
            for (int j = 0; j < 4; j++) {
                int C = cBase + j*8;
                float2 gs = *(const float2*)&ln1s[C];
                float2 gb = *(const float2*)&ln1b[C];
                float2 o2;
                o2.x = (acc[mf][j][2*h+0] - mu) * rinv * gs.x + gb.x;
                o2.y = (acc[mf][j][2*h+1] - mu) * rinv * gs.y + gb.y;
                *(float2*)&g_h1[(size_t)(bl0 + R)*NH + C] = o2;
                g_h1f16[(size_t)(bl0 + R)*64 + (C >> 1)] = pack_f16(o2.x, o2.y);
            }
        }
}

// ---------------------------------------------------------------------------
// ffn1 (mma): H tile [64tok x 128col] = gelu(h1 @ Wi + bi), fp16 out.
// A from g_h1f16 cache via cp.async. grid (64, 4).
// ---------------------------------------------------------------------------
__global__ void __launch_bounds__(256, 3) ffn1_kernel(const float* __restrict__ bi)
{
    extern __shared__ char sm[];
    uint32_t sb = smem_u32(sm);
    int tid = threadIdx.x;
    int wid = tid >> 5, lane = tid & 31;
    int warpM = wid & 1, warpN = wid >> 1;
    int qr = lane >> 2, qc = lane & 3;
    int bl0 = blockIdx.x * 64;
    int nb  = blockIdx.y * 128;
    int cBase = warpN*32 + 2*qc;

    copyB_async(sb + M_B, 6 + blockIdx.y);
    loadA64_cached(sb, g_h1f16, (size_t)bl0, tid);
    CP_COMMIT();
    CP_WAIT0();
    __syncthreads();

    float acc[2][4][4];
    mma_layer64(sb, warpM, warpN, lane, acc);

    #pragma unroll
    for (int mf = 0; mf < 2; mf++)
        #pragma unroll
        for (int j = 0; j < 4; j++) {
            int C = cBase + j*8;
            float2 bv = *(const float2*)&bi[nb + C];
            #pragma unroll
            for (int h = 0; h < 2; h++) {
                int R = warpM*32 + mf*16 + h*8 + qr;
                float v0 = gelu_f(acc[mf][j][2*h+0] + bv.x);
                float v1 = gelu_f(acc[mf][j][2*h+1] + bv.y);
                uint32_t gi = ((uint32_t)(bl0 + R)*FFH + nb + C) >> 1;
                g_Hhi[gi] = pack_f16(v0, v1);
            }
        }
}

// ---------------------------------------------------------------------------
// ffn2 (mma): hV2 = LN2(h1 + H @ Wo + bo) * mask_V, then fused
// P2 = hV2@W11P + b11, G2 = hV2@W11G (fp16 packed). 32 tok/CTA, grid 128.
// ---------------------------------------------------------------------------
#define F2_A   0
#define F2_B   8704
#define F2_STAT 43520
#define SMEM_F2 45568

__device__ __forceinline__ void mma_32(uint32_t sb, int warpM, int warpN,
                                       int lane, float (&acc)[4][4]) {
    #pragma unroll
    for (int j = 0; j < 4; j++)
        #pragma unroll
        for (int c = 0; c < 4; c++) acc[j][c] = 0.0f;
    uint32_t aA = sb + F2_A + (uint32_t)(warpM*16 + (lane & 15))*AST
                + (uint32_t)(lane >> 4)*16;
    uint32_t bB = sb + F2_B + (uint32_t)(lane & 15)*AST
                + (uint32_t)(warpN*4 + (lane >> 4))*16;
    #pragma unroll
    for (int ks = 0; ks < 8; ks++) {
        uint32_t ah[4];
        ldm4(ah, aA + ks*32);
        #pragma unroll
        for (int ng = 0; ng < 2; ng++) {
            uint32_t bh[4];
            ldm4t(bh, bB + ks*16*AST + ng*32);
            mma_f16(acc[2*ng],   ah, bh[0], bh[1]);
            mma_f16(acc[2*ng+1], ah, bh[2], bh[3]);
        }
    }
}

__global__ void __launch_bounds__(256) ffn2_kernel(
    const float* __restrict__ bo,
    const float* __restrict__ ln2s, const float* __restrict__ ln2b,
    const float* __restrict__ mask_V, const float* __restrict__ b11,
    float* __restrict__ out_hV,
    uint32_t* __restrict__ P2, uint32_t* __restrict__ G2)
{
    extern __shared__ char sm[];
    uint32_t sb = smem_u32(sm);
    int tid = threadIdx.x;
    int wid = tid >> 5, lane = tid & 31;
    int warpM = wid & 1, warpN = wid >> 1;   // 2 x 4
    int qr = lane >> 2, qc = lane & 3;
    int bl0 = blockIdx.x * 32;
    int cBase = warpN*32 + 2*qc;

    float acc[4][4];
    #pragma unroll
    for (int j = 0; j < 4; j++)
        #pragma unroll
        for (int c = 0; c < 4; c++) acc[j][c] = 0.0f;

    for (int ch = 0; ch < 4; ch++) {
        {
            int idx = tid;
            #pragma unroll
            for (int i = 0; i < 2; i++) {
                int r = idx >> 4, q4 = (idx & 15) * 4;
                uint32_t gi = (uint32_t)(bl0 + r)*256 + ch*64 + q4;
                cp16(sb + F2_A + r*AST + q4*4, &g_Hhi[gi]);
                idx += 256;
            }
        }
        copyB_async(sb + F2_B, 10 + ch);
        CP_COMMIT();
        CP_WAIT0();
        __syncthreads();

        uint32_t aA = sb + F2_A + (uint32_t)(warpM*16 + (lane & 15))*AST
                    + (uint32_t)(lane >> 4)*16;
        uint32_t bB = sb + F2_B + (uint32_t)(lane & 15)*AST
                    + (uint32_t)(warpN*64 + (lane >> 4)*16);

        #pragma unroll
        for (int ks = 0; ks < 8; ks++) {
            uint32_t ah[4];
            ldm4(ah, aA + ks*32);
            #pragma unroll
            for (int ng = 0; ng < 2; ng++) {
                uint32_t bh[4];
                ldm4t(bh, bB + ks*16*AST + ng*32);
                mma_f16(acc[2*ng],   ah, bh[0], bh[1]);
                mma_f16(acc[2*ng+1], ah, bh[2], bh[3]);
            }
        }
        __syncthreads();
    }

    float* stats = (float*)(sm + F2_STAT);
    float s1[2], s2[2];
    #pragma unroll
    for (int h = 0; h < 2; h++) { s1[h] = 0.f; s2[h] = 0.f; }
    #pragma unroll
    for (int j = 0; j < 4; j++) {
        int C = cBase + j*8;
        float2 bv = *(const float2*)&bo[C];
        #pragma unroll
        for (int h = 0; h < 2; h++) {
            int R = warpM*16 + h*8 + qr;
            float2 hv = *(const float2*)&g_h1[(size_t)(bl0 + R)*NH + C];
            float v0 = acc[j][2*h+0] + bv.x + hv.x;
            float v1 = acc[j][2*h+1] + bv.y + hv.y;
            acc[j][2*h+0] = v0;
            acc[j][2*h+1] = v1;
            s1[h] += v0 + v1;
            s2[h] += v0*v0 + v1*v1;
        }
    }
    #pragma unroll
    for (int h = 0; h < 2; h++) {
        #pragma unroll
        for (int o = 1; o < 4; o <<= 1) {
            s1[h] += __shfl_xor_sync(0xffffffffu, s1[h], o);
            s2[h] += __shfl_xor_sync(0xffffffffu, s2[h], o);
        }
        if (qc == 0) {
            int R = warpM*16 + h*8 + qr;
            stats[(warpN*32 + R)*2 + 0] = s1[h];
            stats[(warpN*32 + R)*2 + 1] = s2[h];
        }
    }
    __syncthreads();
    #pragma unroll
    for (int h = 0; h < 2; h++) {
        int R = warpM*16 + h*8 + qr;
        float S1 = 0.f, S2 = 0.f;
        #pragma unroll
        for (int g = 0; g < 4; g++) {
            S1 += stats[(g*32 + R)*2 + 0];
            S2 += stats[(g*32 + R)*2 + 1];
        }
        float mu = S1 * (1.0f / NH);
        float var = S2 * (1.0f / NH) - mu * mu;
        float rinv = rsqrtf(var + 1e-5f);
        int token = bl0 + R;
        float mk = mask_V[token];
        #pragma unroll
        for (int j = 0; j < 4; j++) {
            int C = cBase + j*8;
            float2 gs = *(const float2*)&ln2s[C];
            float2 gb = *(const float2*)&ln2b[C];
            float2 o2;
            o2.x = ((acc[j][2*h+0] - mu) * rinv * gs.x + gb.x) * mk;
            o2.y = ((acc[j][2*h+1] - mu) * rinv * gs.y + gb.y) * mk;
            *(float2*)&out_hV[(size_t)token*NH + C] = o2;
            *(uint32_t*)(sm + F2_A + R*AST + C*2) = pack_f16(o2.x, o2.y);
        }
    }
    __syncthreads();

    // fused P2 = hV2 @ W11P + b11 (fp16 out)
    copyB_async(sb + F2_B, 16);
    CP_COMMIT();
    CP_WAIT0();
    __syncthreads();
    float acc2[4][4];
    mma_32(sb, warpM, warpN, lane, acc2);
    #pragma unroll
    for (int j = 0; j < 4; j++) {
        int C = cBase + j*8;
        float2 bv = *(const float2*)&b11[C];
        #pragma unroll
        for (int h = 0; h < 2; h++) {
            int R = warpM*16 + h*8 + qr;
            P2[(size_t)(bl0 + R)*64 + (C >> 1)] =
                pack_f16(acc2[j][2*h+0] + bv.x, acc2[j][2*h+1] + bv.y);
        }
    }
    __syncthreads();

    // fused G2 = hV2 @ W11G (fp16 out)
    copyB_async(sb + F2_B, 17);
    CP_COMMIT();
    CP_WAIT0();
    __syncthreads();
    mma_32(sb, warpM, warpN, lane, acc2);
    #pragma unroll
    for (int j = 0; j < 4; j++) {
        int C = cBase + j*8;
        #pragma unroll
        for (int h = 0; h < 2; h++) {
            int R = warpM*16 + h*8 + qr;
            G2[(size_t)(bl0 + R)*64 + (C >> 1)] =
                pack_f16(acc2[j][2*h+0], acc2[j][2*h+1]);
        }
    }
}

// ---------------------------------------------------------------------------

extern "C" void kernel_launch(void* const* d_in, const int* in_sizes, int n_in,
                              void* d_out, int out_size)
{
    const float* h_V         = (const float*)d_in[0];
    const float* h_E         = (const float*)d_in[1];
    const void*  E_idx       =               d_in[2];
    const float* mask_V      = (const float*)d_in[3];
    const float* mask_attend = (const float*)d_in[4];
    const float* W1  = (const float*)d_in[5],  *b1  = (const float*)d_in[6];
    const float* W2  = (const float*)d_in[7],  *b2  = (const float*)d_in[8];
    const float* W3  = (const float*)d_in[9],  *b3  = (const float*)d_in[10];
    const float* W11 = (const float*)d_in[11], *b11 = (const float*)d_in[12];
    const float* W12 = (const float*)d_in[13], *b12 = (const float*)d_in[14];
    const float* W13 = (const float*)d_in[15], *b13 = (const float*)d_in[16];
    const float* Wi  = (const float*)d_in[17], *bi  = (const float*)d_in[18];
    const float* Wo  = (const float*)d_in[19], *bo  = (const float*)d_in[20];
    const float* ln1s = (const float*)d_in[21], *ln1b = (const float*)d_in[22];
    const float* ln2s = (const float*)d_in[23], *ln2b = (const float*)d_in[24];
    const float* ln3s = (const float*)d_in[25], *ln3b = (const float*)d_in[26];
    float* out = (float*)d_out;

    uint32_t *pP1, *pG1, *pP2, *pG2;
    cudaGetSymbolAddress((void**)&pP1,  g_P1);
    cudaGetSymbolAddress((void**)&pG1,  g_G1);
    cudaGetSymbolAddress((void**)&pP2,  g_P2);
    cudaGetSymbolAddress((void**)&pG2,  g_G2);

    cudaFuncSetAttribute(tokenPG_kernel, cudaFuncAttributeMaxDynamicSharedMemorySize, SMEM64);
    cudaFuncSetAttribute(ffn1_kernel,  cudaFuncAttributeMaxDynamicSharedMemorySize, SMEM64);
    cudaFuncSetAttribute(ffn2_kernel,  cudaFuncAttributeMaxDynamicSharedMemorySize, SMEM_F2);
    cudaFuncSetAttribute(nodeFin_kernel, cudaFuncAttributeMaxDynamicSharedMemorySize, SMEMNF);
    cudaFuncSetAttribute(mlp3_kernel<0>, cudaFuncAttributeMaxDynamicSharedMemorySize, SMEM64);
    cudaFuncSetAttribute(mlp3_kernel<1>, cudaFuncAttributeMaxDynamicSharedMemorySize, SMEM64);

    convert_kernel<<<(NEDGE + 255) / 256, 256>>>(E_idx);

    wprep_kernel<<<(18*16384 + 255)/256, 256>>>(W1 + 128*NH, W2, W3,
                                                W11 + 128*NH, W12, W13, Wi, Wo,
                                                W1, W11);

    tokenPG_kernel<<<64, 256, SMEM64>>>(h_V, b1, pP1, pG1);

    mlp3_kernel<0><<<NEDGE/64, 256, SMEM64>>>(h_E, pP1, pG1, b2, nullptr,
                                              mask_attend, nullptr, nullptr,
                                              nullptr, 0);
    nodeFin_kernel<<<64, 256, SMEMNF>>>(h_V, b3, mask_attend, ln1s, ln1b);

    ffn1_kernel<<<dim3(64, 4), 256, SMEM64>>>(bi);
    ffn2_kernel<<<128, 256, SMEM_F2>>>(bo, ln2s, ln2b, mask_V, b11,
                                       out, pP2, pG2);

    mlp3_kernel<1><<<NEDGE/64, 256, SMEM64>>>(h_E, pP2, pG2, b12, b13,
                                              nullptr, ln3s, ln3b,
                                              out + (size_t)NTOK * NH, 3);
}

// round 15
// speedup vs baseline: 1.0860x; 1.0694x over previous
#include <cuda_runtime.h>
#include <cuda_fp16.h>
#include <math.h>
#include <stdint.h>

#define NB 2
#define NL 2048
#define NK 48
#define NH 128
#define NTOK (NB*NL)
#define NEDGE (NB*NL*NK)
#define FFH 512

__device__ int   g_idx32[NEDGE];
__device__ float g_h1 [NTOK*NH];
__device__ uint32_t g_h1f16[NTOK*NH/2];
__device__ uint32_t g_hEf16[NEDGE*NH/2];
__device__ uint32_t g_Hhi[NTOK*FFH/2];
__device__ float g_P1 [NTOK*NH];
__device__ float g_G1 [NTOK*NH];
__device__ float g_P2 [NTOK*NH];
__device__ float g_G2 [NTOK*NH];
__device__ float g_partA[NTOK*NH];
__device__ float g_partB[NTOK*NH];
// 18 fp16 matrices [k][n] (128x128), rows padded to 272B -> 2176 uint4 each
// 0-2 node MLP, 3-5 edge MLP, 6-9 Wi col-tiles, 10-13 Wo k-chunks,
// 14 W1-P, 15 W1-G, 16 W11-P, 17 W11-G
__device__ uint4 g_Wb[18*2176];

#define AST 272
// 64-row tile layout (hi-only A)
#define M_A   0
#define M_B   17408
#define M_STAT 52224
#define SMEM64 54272
#define SMEMNF 54784

__device__ __forceinline__ float gelu_f(float x) {
    return 0.5f * x * (1.0f + erff(x * 0.7071067811865475f));
}

__device__ __forceinline__ uint32_t smem_u32(const void* p) {
    uint32_t a;
    asm("{ .reg .u64 t; cvta.to.shared.u64 t, %1; cvt.u32.u64 %0, t; }"
        : "=r"(a) : "l"(p));
    return a;
}

__device__ __forceinline__ uint32_t pack_f16(float v0, float v1) {
    __half2 h = __floats2half2_rn(v0, v1);
    return *(uint32_t*)&h;
}

__device__ __forceinline__ void cp16(uint32_t dst, const void* src) {
    asm volatile("cp.async.cg.shared.global [%0], [%1], 16;"
        :: "r"(dst), "l"(src));
}
#define CP_COMMIT() asm volatile("cp.async.commit_group;" ::: "memory")
#define CP_WAIT0()  asm volatile("cp.async.wait_group 0;" ::: "memory")
#define PREF_L2(p)  asm volatile("prefetch.global.L2 [%0];" :: "l"(p))

__device__ __forceinline__ void ldm4(uint32_t r[4], uint32_t a) {
    asm volatile("ldmatrix.sync.aligned.m8n8.x4.shared.b16 {%0,%1,%2,%3}, [%4];"
        : "=r"(r[0]), "=r"(r[1]), "=r"(r[2]), "=r"(r[3]) : "r"(a));
}
__device__ __forceinline__ void ldm4t(uint32_t r[4], uint32_t a) {
    asm volatile("ldmatrix.sync.aligned.m8n8.x4.trans.shared.b16 {%0,%1,%2,%3}, [%4];"
        : "=r"(r[0]), "=r"(r[1]), "=r"(r[2]), "=r"(r[3]) : "r"(a));
}
__device__ __forceinline__ void mma_f16(float c[4], const uint32_t a[4],
                                        uint32_t b0, uint32_t b1) {
    asm volatile(
        "mma.sync.aligned.m16n8k16.row.col.f32.f16.f16.f32 "
        "{%0,%1,%2,%3}, {%4,%5,%6,%7}, {%8,%9}, {%0,%1,%2,%3};"
        : "+f"(c[0]), "+f"(c[1]), "+f"(c[2]), "+f"(c[3])
        : "r"(a[0]), "r"(a[1]), "r"(a[2]), "r"(a[3]), "r"(b0), "r"(b1));
}

// ---------------------------------------------------------------------------
// convert: dtype detect (per-block, redundant) + normalize E_idx to int32.
// ---------------------------------------------------------------------------
__global__ void convert_kernel(const void* __restrict__ e) {
    __shared__ int s_is64;
    if (threadIdx.x == 0) {
        const int* w = (const int*)e;
        int nz = 0;
        #pragma unroll 8
        for (int i = 1; i < 256; i += 2) nz |= (w[i] != 0);
        s_is64 = (nz == 0);
    }
    __syncthreads();
    int i = blockIdx.x * blockDim.x + threadIdx.x;
    if (i >= NEDGE) return;
    if (s_is64) g_idx32[i] = (int)((const long long*)e)[i];
    else        g_idx32[i] = ((const int*)e)[i];
}

// ---------------------------------------------------------------------------
// wprep: all weights -> fp16 tiles [k][n], rows padded to 272B.
// ---------------------------------------------------------------------------
__global__ void wprep_kernel(const float* W0, const float* W1, const float* W2,
                             const float* W3, const float* W4, const float* W5,
                             const float* Wi, const float* Wo,
                             const float* W1full, const float* W11full) {
    int gid = blockIdx.x * 256 + threadIdx.x;
    if (gid >= 18 * 16384) return;
    int m = gid >> 14, rem = gid & 16383;
    int k = rem >> 7, n = rem & 127;
    float v;
    if (m < 6) {
        const float* W = (m == 0) ? W0 : (m == 1) ? W1 : (m == 2) ? W2
                       : (m == 3) ? W3 : (m == 4) ? W4 : W5;
        v = W[k * 128 + n];
    } else if (m < 10) {
        v = Wi[k * FFH + (m - 6) * 128 + n];
    } else if (m < 14) {
        v = Wo[((m - 10) * 128 + k) * 128 + n];
    } else if (m == 14) {
        v = W1full[k * 128 + n];
    } else if (m == 15) {
        v = W1full[(256 + k) * 128 + n];
    } else if (m == 16) {
        v = W11full[k * 128 + n];
    } else {
        v = W11full[(256 + k) * 128 + n];
    }
    char* basep = (char*)g_Wb + (size_t)m * 34816;
    *(__half*)(basep + (uint32_t)k * 272u + (uint32_t)n * 2u) = __float2half_rn(v);
}

// ---------------------------------------------------------------------------
// Shared mma machinery: 64 rows x 128 cols, K=128, single-pass fp16.
// 8 warps = 2(M) x 4(N).
// ---------------------------------------------------------------------------
__device__ __forceinline__ void copyB_async(uint32_t dst, int mat) {
    const uint4* src = &g_Wb[(size_t)mat * 2176];
    #pragma unroll
    for (int i = 0; i < 9; i++) {
        int idx = threadIdx.x + 256*i;
        if (idx < 2176) cp16(dst + idx*16, src + idx);
    }
}

__device__ __forceinline__ void mma_layer64(uint32_t sb, int warpM, int warpN,
                                            int lane, float (&acc)[2][4][4]) {
    #pragma unroll
    for (int m = 0; m < 2; m++)
        #pragma unroll
        for (int j = 0; j < 4; j++)
            #pragma unroll
            for (int c = 0; c < 4; c++) acc[m][j][c] = 0.0f;

    uint32_t aA = sb + M_A + (uint32_t)(warpM*32 + (lane & 15))*AST
                + (uint32_t)(lane >> 4)*16;
    uint32_t bB = sb + M_B + (uint32_t)(lane & 15)*AST
                + (uint32_t)(warpN*4 + (lane >> 4))*16;

    #pragma unroll
    for (int ks = 0; ks < 8; ks++) {
        uint32_t ah0[4], ah1[4];
        ldm4(ah0, aA + ks*32);
        ldm4(ah1, aA + ks*32 + 16*AST);
        #pragma unroll
        for (int ng = 0; ng < 2; ng++) {
            uint32_t bh[4];
            ldm4t(bh, bB + ks*16*AST + ng*32);
            mma_f16(acc[0][2*ng],   ah0, bh[0], bh[1]);
            mma_f16(acc[1][2*ng],   ah1, bh[0], bh[1]);
            mma_f16(acc[0][2*ng+1], ah0, bh[2], bh[3]);
            mma_f16(acc[1][2*ng+1], ah1, bh[2], bh[3]);
        }
    }
}

// load 64 fp32 rows -> fp16 into smem
__device__ __forceinline__ void loadA64(char* sm, const float* src, int tid) {
    for (int idx = tid; idx < 64*64; idx += 256) {
        int r = idx >> 6, cp = idx & 63;
        float2 x = *(const float2*)&src[(size_t)r*NH + cp*2];
        *(uint32_t*)(sm + M_A + r*AST + cp*4) = pack_f16(x.x, x.y);
    }
}

// cp.async 64 fp16 rows from packed cache (row stride 64 uint32)
__device__ __forceinline__ void loadA64_cached(uint32_t sb, const uint32_t* cache,
                                               size_t row0, int tid) {
    #pragma unroll
    for (int i = 0; i < 4; i++) {
        int idx = tid + 256*i;          // 1024 x 16B
        int r = idx >> 4, q4 = (idx & 15) * 4;
        cp16(sb + M_A + r*AST + q4*4, &cache[(row0 + r)*64 + q4]);
    }
}

// ---------------------------------------------------------------------------
// tokenPG fused: P = A@W14 + b ; G = A@W15. grid 64.
// ---------------------------------------------------------------------------
__global__ void __launch_bounds__(256, 3) tokenPG_kernel(
    const float* __restrict__ A, const float* __restrict__ bias,
    float* __restrict__ P, float* __restrict__ G)
{
    extern __shared__ char sm[];
    uint32_t sb = smem_u32(sm);
    int tid = threadIdx.x;
    int wid = tid >> 5, lane = tid & 31;
    int warpM = wid & 1, warpN = wid >> 1;
    int qr = lane >> 2, qc = lane & 3;
    int bl0 = blockIdx.x * 64;
    int cBase = warpN*32 + 2*qc;

    copyB_async(sb + M_B, 14);
    CP_COMMIT();
    loadA64(sm, A + (size_t)bl0*NH, tid);
    CP_WAIT0();
    __syncthreads();

    float acc[2][4][4];
    mma_layer64(sb, warpM, warpN, lane, acc);
    __syncthreads();
    copyB_async(sb + M_B, 15);
    CP_COMMIT();

    #pragma unroll
    for (int mf = 0; mf < 2; mf++)
        #pragma unroll
        for (int j = 0; j < 4; j++) {
            int C = cBase + j*8;
            float2 bv = *(const float2*)&bias[C];
            #pragma unroll
            for (int h = 0; h < 2; h++) {
                int R = warpM*32 + mf*16 + h*8 + qr;
                float2 o2;
                o2.x = acc[mf][j][2*h+0] + bv.x;
                o2.y = acc[mf][j][2*h+1] + bv.y;
                *(float2*)&P[(size_t)(bl0 + R)*NH + C] = o2;
            }
        }
    CP_WAIT0();
    __syncthreads();

    mma_layer64(sb, warpM, warpN, lane, acc);
    #pragma unroll
    for (int mf = 0; mf < 2; mf++)
        #pragma unroll
        for (int j = 0; j < 4; j++) {
            int C = cBase + j*8;
            #pragma unroll
            for (int h = 0; h < 2; h++) {
                int R = warpM*32 + mf*16 + h*8 + qr;
                float2 o2;
                o2.x = acc[mf][j][2*h+0];
                o2.y = acc[mf][j][2*h+1];
                *(float2*)&G[(size_t)(bl0 + R)*NH + C] = o2;
            }
        }
}

// ---------------------------------------------------------------------------
// mlp3: 64 edge rows per CTA, occ=4. MODE 0 = node (2 layers + masked
// Z row-sum; writes hE fp16 cache). MODE 1 = edge (3 layers + LN3).
// ---------------------------------------------------------------------------
template<int MODE>
__global__ void __launch_bounds__(256, 4) mlp3_kernel(
    const float* __restrict__ hE,
    const float* __restrict__ P, const float* __restrict__ G,
    const float* __restrict__ bias2, const float* __restrict__ bias3,
    const float* __restrict__ mask_attend,
    const float* __restrict__ ln3s, const float* __restrict__ ln3b,
    float* __restrict__ out_hE, int matBase)
{
    extern __shared__ char sm[];
    uint32_t sb = smem_u32(sm);

    int tid = threadIdx.x;
    int wid = tid >> 5, lane = tid & 31;
    int warpM = wid & 1, warpN = wid >> 1;
    int qr = lane >> 2, qc = lane & 3;
    int e0 = blockIdx.x * 64;
    int cBase = warpN*32 + 2*qc;

    int Row[2][2];
    #pragma unroll
    for (int mf = 0; mf < 2; mf++)
        #pragma unroll
        for (int h = 0; h < 2; h++)
            Row[mf][h] = warpM*32 + mf*16 + h*8 + qr;

    copyB_async(sb + M_B, matBase + 0);
    if (MODE == 0) {
        CP_COMMIT();
        // convert hE -> fp16 smem + write cache
        for (int idx = tid; idx < 64*64; idx += 256) {
            int r = idx >> 6, cp = idx & 63;
            float2 x = *(const float2*)&hE[(size_t)(e0 + r)*NH + cp*2];
            uint32_t u = pack_f16(x.x, x.y);
            *(uint32_t*)(sm + M_A + r*AST + cp*4) = u;
            g_hEf16[(size_t)(e0 + r)*64 + cp] = u;
        }
    } else {
        loadA64_cached(sb, g_hEf16, (size_t)e0, tid);
        CP_COMMIT();
    }
    // L2 prefetch of P/G gather rows for epilogue 1
    {
        int r = tid >> 2, ln = tid & 3;
        int e = e0 + r;
        int tok = e / 48;
        int batch = (e >= NL*NK) ? 1 : 0;
        PREF_L2(&P[(size_t)tok*NH + ln*32]);
        PREF_L2(&G[(size_t)(batch*NL + g_idx32[e])*NH + ln*32]);
    }
    CP_WAIT0();
    __syncthreads();

    float acc[2][4][4];

    // ---- layer 1 ----
    mma_layer64(sb, warpM, warpN, lane, acc);
    __syncthreads();
    copyB_async(sb + M_B, matBase + 1);
    CP_COMMIT();
    {
        const float* Pr[2][2];
        const float* Gr[2][2];
        #pragma unroll
        for (int mf = 0; mf < 2; mf++)
            #pragma unroll
            for (int h = 0; h < 2; h++) {
                int e = e0 + Row[mf][h];
                int tok = e / 48;
                int batch = (e >= NL*NK) ? 1 : 0;
                Pr[mf][h] = P + (size_t)tok * NH;
                Gr[mf][h] = G + (size_t)(batch*NL + g_idx32[e]) * NH;
            }
        #pragma unroll
        for (int mf = 0; mf < 2; mf++)
            #pragma unroll
            for (int j = 0; j < 4; j++) {
                int C = cBase + j*8;
                #pragma unroll
                for (int h = 0; h < 2; h++) {
                    float2 pv = *(const float2*)&Pr[mf][h][C];
                    float2 gv = *(const float2*)&Gr[mf][h][C];
                    float v0 = gelu_f(acc[mf][j][2*h+0] + pv.x + gv.x);
                    float v1 = gelu_f(acc[mf][j][2*h+1] + pv.y + gv.y);
                    int R = Row[mf][h];
                    *(uint32_t*)(sm + M_A + R*AST + C*2) = pack_f16(v0, v1);
                }
            }
    }
    CP_WAIT0();
    __syncthreads();

    // ---- layer 2 ----
    mma_layer64(sb, warpM, warpN, lane, acc);
    __syncthreads();

    if (MODE == 0) {
        // Z = gelu(acc + b2); stage Z*mask (fp32); per-token row-sum -> partials
        float* stage = (float*)(sm + M_A);  // [64][136] f32 (aliases A+B)
        #pragma unroll
        for (int mf = 0; mf < 2; mf++)
            #pragma unroll
            for (int h = 0; h < 2; h++) {
                int R = Row[mf][h];
                float mk = mask_attend[e0 + R];
                #pragma unroll
                for (int j = 0; j < 4; j++) {
                    int C = cBase + j*8;
                    float2 bv = *(const float2*)&bias2[C];
                    float2 o2;
                    o2.x = gelu_f(acc[mf][j][2*h+0] + bv.x) * mk;
                    o2.y = gelu_f(acc[mf][j][2*h+1] + bv.y) * mk;
                    *(float2*)&stage[R*136 + C] = o2;
                }
            }
        __syncthreads();
        int t0 = e0 / 48;
        int tend = (e0 + 63) / 48;
        for (int t = t0 + (tid >> 7); t <= tend; t += 2) {
            int col = tid & 127;
            int rs = max(t*48 - e0, 0), re = min(t*48 + 47 - e0, 63);
            float sacc = 0.0f;
            for (int rr = rs; rr <= re; rr++) sacc += stage[rr*136 + col];
            if (t*48 >= e0) g_partA[(size_t)t*NH + col] = sacc;
            else            g_partB[(size_t)t*NH + col] = sacc;
        }
        return;
    }

    // ---- edge path: layer-2 epilogue, layer 3, LN3 ----
    copyB_async(sb + M_B, matBase + 2);
    CP_COMMIT();
    #pragma unroll
    for (int mf = 0; mf < 2; mf++)
        #pragma unroll
        for (int j = 0; j < 4; j++) {
            int C = cBase + j*8;
            float2 bv = *(const float2*)&bias2[C];
            #pragma unroll
            for (int h = 0; h < 2; h++) {
                float v0 = gelu_f(acc[mf][j][2*h+0] + bv.x);
                float v1 = gelu_f(acc[mf][j][2*h+1] + bv.y);
                int R = Row[mf][h];
                *(uint32_t*)(sm + M_A + R*AST + C*2) = pack_f16(v0, v1);
            }
        }
    CP_WAIT0();
    __syncthreads();

    mma_layer64(sb, warpM, warpN, lane, acc);
    __syncthreads();

    float* stats = (float*)(sm + M_STAT);   // [4 warpN][64 rows][2]
    float s1[2][2], s2[2][2];
    #pragma unroll
    for (int mf = 0; mf < 2; mf++)
        #pragma unroll
        for (int h = 0; h < 2; h++) { s1[mf][h] = 0.f; s2[mf][h] = 0.f; }
    #pragma unroll
    for (int mf = 0; mf < 2; mf++)
        #pragma unroll
        for (int j = 0; j < 4; j++) {
            int C = cBase + j*8;
            float2 bv = *(const float2*)&bias3[C];
            #pragma unroll
            for (int h = 0; h < 2; h++) {
                int R = Row[mf][h];
                float2 he = *(const float2*)&hE[(size_t)(e0 + R)*NH + C];
                float v0 = acc[mf][j][2*h+0] + bv.x + he.x;
                float v1 = acc[mf][j][2*h+1] + bv.y + he.y;
                acc[mf][j][2*h+0] = v0;
                acc[mf][j][2*h+1] = v1;
                s1[mf][h] += v0 + v1;
                s2[mf][h] += v0*v0 + v1*v1;
            }
        }
    #pragma unroll
    for (int mf = 0; mf < 2; mf++)
        #pragma unroll
        for (int h = 0; h < 2; h++) {
            #pragma unroll
            for (int o = 1; o < 4; o <<= 1) {
                s1[mf][h] += __shfl_xor_sync(0xffffffffu, s1[mf][h], o);
                s2[mf][h] += __shfl_xor_sync(0xffffffffu, s2[mf][h], o);
            }
            if (qc == 0) {
                stats[(warpN*64 + Row[mf][h])*2 + 0] = s1[mf][h];
                stats[(warpN*64 + Row[mf][h])*2 + 1] = s2[mf][h];
            }
        }
    __syncthreads();
    #pragma unroll
    for (int mf = 0; mf < 2; mf++)
        #pragma unroll
        for (int h = 0; h < 2; h++) {
            int R = Row[mf][h];
            float S1 = 0.f, S2 = 0.f;
            #pragma unroll
            for (int g = 0; g < 4; g++) {
                S1 += stats[(g*64 + R)*2 + 0];
                S2 += stats[(g*64 + R)*2 + 1];
            }
            float mu = S1 * (1.0f / NH);
            float var = S2 * (1.0f / NH) - mu * mu;
            float rinv = rsqrtf(var + 1e-5f);
            #pragma unroll
            for (int j = 0; j < 4; j++) {
                int C = cBase + j*8;
                float2 gs = *(const float2*)&ln3s[C];
                float2 gb = *(const float2*)&ln3b[C];
                float2 o2;
                o2.x = (acc[mf][j][2*h+0] - mu) * rinv * gs.x + gb.x;
                o2.y = (acc[mf][j][2*h+1] - mu) * rinv * gs.y + gb.y;
                *(float2*)&out_hE[(size_t)(e0 + R)*NH + C] = o2;
            }
        }
}

// ---------------------------------------------------------------------------
// nodeFin: dh = S@W3 + (Σmask)*b3 ; h1 = LN1(hV + dh/30). 64 tokens/CTA.
// Writes g_h1 (fp32) and g_h1f16 (packed) for ffn1.
// ---------------------------------------------------------------------------
__global__ void __launch_bounds__(256) nodeFin_kernel(
    const float* __restrict__ hV, const float* __restrict__ b3,
    const float* __restrict__ mask_attend,
    const float* __restrict__ ln1s, const float* __restrict__ ln1b)
{
    extern __shared__ char sm[];
    uint32_t sb = smem_u32(sm);
    int tid = threadIdx.x;
    int wid = tid >> 5, lane = tid & 31;
    int warpM = wid & 1, warpN = wid >> 1;
    int qr = lane >> 2, qc = lane & 3;
    int bl0 = blockIdx.x * 64;
    int cBase = warpN*32 + 2*qc;

    copyB_async(sb + M_B, 2);   // W3
    CP_COMMIT();
    for (int idx = tid; idx < 64*64; idx += 256) {
        int r = idx >> 6, cp = idx & 63;
        int t = bl0 + r;
        float2 x = *(const float2*)&g_partA[(size_t)t*NH + cp*2];
        int s0 = t * 48;
        if (s0 / 64 != (s0 + 47) / 64) {
            float2 y = *(const float2*)&g_partB[(size_t)t*NH + cp*2];
            x.x += y.x; x.y += y.y;
        }
        *(uint32_t*)(sm + M_A + r*AST + cp*4) = pack_f16(x.x, x.y);
    }
    CP_WAIT0();
    __syncthreads();

    float acc[2][4][4];
    mma_layer64(sb, warpM, warpN, lane, acc);

    float* stats = (float*)(sm + M_STAT);
    float* msum  = (float*)(sm + M_STAT + 2048);
    if (tid < 64) {
        int t = bl0 + tid;
        float s = 0.0f;
        #pragma unroll 4
        for (int k = 0; k < NK; k += 4) {
            float4 m4 = *(const float4*)&mask_attend[t*NK + k];
            s += m4.x + m4.y + m4.z + m4.w;
        }
        msum[tid] = s;
    }
    __syncthreads();

    int Row[2][2];
    #pragma unroll
    for (int mf = 0; mf < 2; mf++)
        #pragma unroll
        for (int h = 0; h < 2; h++)
            Row[mf][h] = warpM*32 + mf*16 + h*8 + qr;

    float s1[2][2], s2[2][2];
    #pragma unroll
    for (int mf = 0; mf < 2; mf++)
        #pragma unroll
        for (int h = 0; h < 2; h++) { s1[mf][h] = 0.f; s2[mf][h] = 0.f; }

    #pragma unroll
    for (int mf = 0; mf < 2; mf++)
        #pragma unroll
        for (int j = 0; j < 4; j++) {
            int C = cBase + j*8;
            float2 bv = *(const float2*)&b3[C];
            #pragma unroll
            for (int h = 0; h < 2; h++) {
                int R = Row[mf][h];
                int t = bl0 + R;
                float ms = msum[R];
                float2 hv = *(const float2*)&hV[(size_t)t*NH + C];
                float v0 = hv.x + (acc[mf][j][2*h+0] + ms*bv.x) * (1.0f/30.0f);
                float v1 = hv.y + (acc[mf][j][2*h+1] + ms*bv.y) * (1.0f/30.0f);
                acc[mf][j][2*h+0] = v0;
                acc[mf][j][2*h+1] = v1;
                s1[mf][h] += v0 + v1;
                s2[mf][h] += v0*v0 + v1*v1;
            }
        }
    #pragma unroll
    for (int mf = 0; mf < 2; mf++)
        #pragma unroll
        for (int h = 0; h < 2; h++) {
            #pragma unroll
            for (int o = 1; o < 4; o <<= 1) {
                s1[mf][h] += __shfl_xor_sync(0xffffffffu, s1[mf][h], o);
                s2[mf][h] += __shfl_xor_sync(0xffffffffu, s2[mf][h], o);
            }
            if (qc == 0) {
                stats[(warpN*64 + Row[mf][h])*2 + 0] = s1[mf][h];
                stats[(warpN*64 + Row[mf][h])*2 + 1] = s2[mf][h];
            }
        }
    __syncthreads();
    #pragma unroll
    for (int mf = 0; mf < 2; mf++)
        #pragma unroll
        for (int h = 0; h < 2; h++) {
            int R = Row[mf][h];
            float S1 = 0.f, S2 = 0.f;
            #pragma unroll
            for (int g = 0; g < 4; g++) {
                S1 += stats[(g*64 + R)*2 + 0];
                S2 += stats[(g*64 + R)*2 + 1];
            }
            float mu = S1 * (1.0f / NH);
            float var = S2 * (1.0f / NH) - mu * mu;
            float rinv = rsqrtf(var + 1e-5f);
            #pragma unroll
            for (int j = 0; j < 4; j++) {
                int C = cBase + j*8;
                float2 gs = *(const float2*)&ln1s[C];
                float2 gb = *(const float2*)&ln1b[C];
                float2 o2;
                o2.x = (acc[mf][j][2*h+0] - mu) * rinv * gs.x + gb.x;
                o2.y = (acc[mf][j][2*h+1] - mu) * rinv * gs.y + gb.y;
                *(float2*)&g_h1[(size_t)(bl0 + R)*NH + C] = o2;
                g_h1f16[(size_t)(bl0 + R)*64 + (C >> 1)] = pack_f16(o2.x, o2.y);
            }
        }
}

// ---------------------------------------------------------------------------
// ffn1 (mma): H tile [64tok x 128col] = gelu(h1 @ Wi + bi), fp16 out.
// A from g_h1f16 cache via cp.async. grid (64, 4).
// ---------------------------------------------------------------------------
__global__ void __launch_bounds__(256, 3) ffn1_kernel(const float* __restrict__ bi)
{
    extern __shared__ char sm[];
    uint32_t sb = smem_u32(sm);
    int tid = threadIdx.x;
    int wid = tid >> 5, lane = tid & 31;
    int warpM = wid & 1, warpN = wid >> 1;
    int qr = lane >> 2, qc = lane & 3;
    int bl0 = blockIdx.x * 64;
    int nb  = blockIdx.y * 128;
    int cBase = warpN*32 + 2*qc;

    copyB_async(sb + M_B, 6 + blockIdx.y);
    loadA64_cached(sb, g_h1f16, (size_t)bl0, tid);
    CP_COMMIT();
    CP_WAIT0();
    __syncthreads();

    float acc[2][4][4];
    mma_layer64(sb, warpM, warpN, lane, acc);

    #pragma unroll
    for (int mf = 0; mf < 2; mf++)
        #pragma unroll
        for (int j = 0; j < 4; j++) {
            int C = cBase + j*8;
            float2 bv = *(const float2*)&bi[nb + C];
            #pragma unroll
            for (int h = 0; h < 2; h++) {
                int R = warpM*32 + mf*16 + h*8 + qr;
                float v0 = gelu_f(acc[mf][j][2*h+0] + bv.x);
                float v1 = gelu_f(acc[mf][j][2*h+1] + bv.y);
                uint32_t gi = ((uint32_t)(bl0 + R)*FFH + nb + C) >> 1;
                g_Hhi[gi] = pack_f16(v0, v1);
            }
        }
}

// ---------------------------------------------------------------------------
// ffn2 (mma): hV2 = LN2(h1 + H @ Wo + bo) * mask_V, then fused
// P2 = hV2@W11P + b11, G2 = hV2@W11G. 32 tok/CTA, grid 128.
// ---------------------------------------------------------------------------
#define F2_A   0
#define F2_B   8704
#define F2_STAT 43520
#define SMEM_F2 45568

__device__ __forceinline__ void mma_32(uint32_t sb, int warpM, int warpN,
                                       int lane, float (&acc)[4][4]) {
    #pragma unroll
    for (int j = 0; j < 4; j++)
        #pragma unroll
        for (int c = 0; c < 4; c++) acc[j][c] = 0.0f;
    uint32_t aA = sb + F2_A + (uint32_t)(warpM*16 + (lane & 15))*AST
                + (uint32_t)(lane >> 4)*16;
    uint32_t bB = sb + F2_B + (uint32_t)(lane & 15)*AST
                + (uint32_t)(warpN*4 + (lane >> 4))*16;
    #pragma unroll
    for (int ks = 0; ks < 8; ks++) {
        uint32_t ah[4];
        ldm4(ah, aA + ks*32);
        #pragma unroll
        for (int ng = 0; ng < 2; ng++) {
            uint32_t bh[4];
            ldm4t(bh, bB + ks*16*AST + ng*32);
            mma_f16(acc[2*ng],   ah, bh[0], bh[1]);
            mma_f16(acc[2*ng+1], ah, bh[2], bh[3]);
        }
    }
}

__global__ void __launch_bounds__(256) ffn2_kernel(
    const float* __restrict__ bo,
    const float* __restrict__ ln2s, const float* __restrict__ ln2b,
    const float* __restrict__ mask_V, const float* __restrict__ b11,
    float* __restrict__ out_hV, float* __restrict__ P2, float* __restrict__ G2)
{
    extern __shared__ char sm[];
    uint32_t sb = smem_u32(sm);
    int tid = threadIdx.x;
    int wid = tid >> 5, lane = tid & 31;
    int warpM = wid & 1, warpN = wid >> 1;   // 2 x 4
    int qr = lane >> 2, qc = lane & 3;
    int bl0 = blockIdx.x * 32;
    int cBase = warpN*32 + 2*qc;

    float acc[4][4];
    #pragma unroll
    for (int j = 0; j < 4; j++)
        #pragma unroll
        for (int c = 0; c < 4; c++) acc[j][c] = 0.0f;

    for (int ch = 0; ch < 4; ch++) {
        {
            int idx = tid;
            #pragma unroll
            for (int i = 0; i < 2; i++) {
                int r = idx >> 4, q4 = (idx & 15) * 4;
                uint32_t gi = (uint32_t)(bl0 + r)*256 + ch*64 + q4;
                cp16(sb + F2_A + r*AST + q4*4, &g_Hhi[gi]);
                idx += 256;
            }
        }
        copyB_async(sb + F2_B, 10 + ch);
        CP_COMMIT();
        CP_WAIT0();
        __syncthreads();

        uint32_t aA = sb + F2_A + (uint32_t)(warpM*16 + (lane & 15))*AST
                    + (uint32_t)(lane >> 4)*16;
        uint32_t bB = sb + F2_B + (uint32_t)(lane & 15)*AST
                    + (uint32_t)(warpN*64 + (lane >> 4)*16);

        #pragma unroll
        for (int ks = 0; ks < 8; ks++) {
            uint32_t ah[4];
            ldm4(ah, aA + ks*32);
            #pragma unroll
            for (int ng = 0; ng < 2; ng++) {
                uint32_t bh[4];
                ldm4t(bh, bB + ks*16*AST + ng*32);
                mma_f16(acc[2*ng],   ah, bh[0], bh[1]);
                mma_f16(acc[2*ng+1], ah, bh[2], bh[3]);
            }
        }
        __syncthreads();
    }

    float* stats = (float*)(sm + F2_STAT);
    float s1[2], s2[2];
    #pragma unroll
    for (int h = 0; h < 2; h++) { s1[h] = 0.f; s2[h] = 0.f; }
    #pragma unroll
    for (int j = 0; j < 4; j++) {
        int C = cBase + j*8;
        float2 bv = *(const float2*)&bo[C];
        #pragma unroll
        for (int h = 0; h < 2; h++) {
            int R = warpM*16 + h*8 + qr;
            float2 hv = *(const float2*)&g_h1[(size_t)(bl0 + R)*NH + C];
            float v0 = acc[j][2*h+0] + bv.x + hv.x;
            float v1 = acc[j][2*h+1] + bv.y + hv.y;
            acc[j][2*h+0] = v0;
            acc[j][2*h+1] = v1;
            s1[h] += v0 + v1;
            s2[h] += v0*v0 + v1*v1;
        }
    }
    #pragma unroll
    for (int h = 0; h < 2; h++) {
        #pragma unroll
        for (int o = 1; o < 4; o <<= 1) {
            s1[h] += __shfl_xor_sync(0xffffffffu, s1[h], o);
            s2[h] += __shfl_xor_sync(0xffffffffu, s2[h], o);
        }
        if (qc == 0) {
            int R = warpM*16 + h*8 + qr;
            stats[(warpN*32 + R)*2 + 0] = s1[h];
            stats[(warpN*32 + R)*2 + 1] = s2[h];
        }
    }
    __syncthreads();
    #pragma unroll
    for (int h = 0; h < 2; h++) {
        int R = warpM*16 + h*8 + qr;
        float S1 = 0.f, S2 = 0.f;
        #pragma unroll
        for (int g = 0; g < 4; g++) {
            S1 += stats[(g*32 + R)*2 + 0];
            S2 += stats[(g*32 + R)*2 + 1];
        }
        float mu = S1 * (1.0f / NH);
        float var = S2 * (1.0f / NH) - mu * mu;
        float rinv = rsqrtf(var + 1e-5f);
        int token = bl0 + R;
        float mk = mask_V[token];
        #pragma unroll
        for (int j = 0; j < 4; j++) {
            int C = cBase + j*8;
            float2 gs = *(const float2*)&ln2s[C];
            float2 gb = *(const float2*)&ln2b[C];
            float2 o2;
            o2.x = ((acc[j][2*h+0] - mu) * rinv * gs.x + gb.x) * mk;
            o2.y = ((acc[j][2*h+1] - mu) * rinv * gs.y + gb.y) * mk;
            *(float2*)&out_hV[(size_t)token*NH + C] = o2;
            *(uint32_t*)(sm + F2_A + R*AST + C*2) = pack_f16(o2.x, o2.y);
        }
    }
    __syncthreads();

    // fused P2 = hV2 @ W11P + b11
    copyB_async(sb + F2_B, 16);
    CP_COMMIT();
    CP_WAIT0();
    __syncthreads();
    float acc2[4][4];
    mma_32(sb, warpM, warpN, lane, acc2);
    #pragma unroll
    for (int j = 0; j < 4; j++) {
        int C = cBase + j*8;
        float2 bv = *(const float2*)&b11[C];
        #pragma unroll
        for (int h = 0; h < 2; h++) {
            int R = warpM*16 + h*8 + qr;
            float2 o2;
            o2.x = acc2[j][2*h+0] + bv.x;
            o2.y = acc2[j][2*h+1] + bv.y;
            *(float2*)&P2[(size_t)(bl0 + R)*NH + C] = o2;
        }
    }
    __syncthreads();

    // fused G2 = hV2 @ W11G
    copyB_async(sb + F2_B, 17);
    CP_COMMIT();
    CP_WAIT0();
    __syncthreads();
    mma_32(sb, warpM, warpN, lane, acc2);
    #pragma unroll
    for (int j = 0; j < 4; j++) {
        int C = cBase + j*8;
        #pragma unroll
        for (int h = 0; h < 2; h++) {
            int R = warpM*16 + h*8 + qr;
            float2 o2;
            o2.x = acc2[j][2*h+0];
            o2.y = acc2[j][2*h+1];
            *(float2*)&G2[(size_t)(bl0 + R)*NH + C] = o2;
        }
    }
}

// ---------------------------------------------------------------------------

extern "C" void kernel_launch(void* const* d_in, const int* in_sizes, int n_in,
                              void* d_out, int out_size)
{
    const float* h_V         = (const float*)d_in[0];
    const float* h_E         = (const float*)d_in[1];
    const void*  E_idx       =               d_in[2];
    const float* mask_V      = (const float*)d_in[3];
    const float* mask_attend = (const float*)d_in[4];
    const float* W1  = (const float*)d_in[5],  *b1  = (const float*)d_in[6];
    const float* W2  = (const float*)d_in[7],  *b2  = (const float*)d_in[8];
    const float* W3  = (const float*)d_in[9],  *b3  = (const float*)d_in[10];
    const float* W11 = (const float*)d_in[11], *b11 = (const float*)d_in[12];
    const float* W12 = (const float*)d_in[13], *b12 = (const float*)d_in[14];
    const float* W13 = (const float*)d_in[15], *b13 = (const float*)d_in[16];
    const float* Wi  = (const float*)d_in[17], *bi  = (const float*)d_in[18];
    const float* Wo  = (const float*)d_in[19], *bo  = (const float*)d_in[20];
    const float* ln1s = (const float*)d_in[21], *ln1b = (const float*)d_in[22];
    const float* ln2s = (const float*)d_in[23], *ln2b = (const float*)d_in[24];
    const float* ln3s = (const float*)d_in[25], *ln3b = (const float*)d_in[26];
    float* out = (float*)d_out;

    float *pP1, *pG1, *pP2, *pG2;
    cudaGetSymbolAddress((void**)&pP1,  g_P1);
    cudaGetSymbolAddress((void**)&pG1,  g_G1);
    cudaGetSymbolAddress((void**)&pP2,  g_P2);
    cudaGetSymbolAddress((void**)&pG2,  g_G2);

    cudaFuncSetAttribute(tokenPG_kernel, cudaFuncAttributeMaxDynamicSharedMemorySize, SMEM64);
    cudaFuncSetAttribute(ffn1_kernel,  cudaFuncAttributeMaxDynamicSharedMemorySize, SMEM64);
    cudaFuncSetAttribute(ffn2_kernel,  cudaFuncAttributeMaxDynamicSharedMemorySize, SMEM_F2);
    cudaFuncSetAttribute(nodeFin_kernel, cudaFuncAttributeMaxDynamicSharedMemorySize, SMEMNF);
    cudaFuncSetAttribute(mlp3_kernel<0>, cudaFuncAttributeMaxDynamicSharedMemorySize, SMEM64);
    cudaFuncSetAttribute(mlp3_kernel<1>, cudaFuncAttributeMaxDynamicSharedMemorySize, SMEM64);

    convert_kernel<<<(NEDGE + 255) / 256, 256>>>(E_idx);

    wprep_kernel<<<(18*16384 + 255)/256, 256>>>(W1 + 128*NH, W2, W3,
                                                W11 + 128*NH, W12, W13, Wi, Wo,
                                                W1, W11);

    tokenPG_kernel<<<64, 256, SMEM64>>>(h_V, b1, pP1, pG1);

    mlp3_kernel<0><<<NEDGE/64, 256, SMEM64>>>(h_E, pP1, pG1, b2, nullptr,
                                              mask_attend, nullptr, nullptr,
                                              nullptr, 0);
    nodeFin_kernel<<<64, 256, SMEMNF>>>(h_V, b3, mask_attend, ln1s, ln1b);

    ffn1_kernel<<<dim3(64, 4), 256, SMEM64>>>(bi);
    ffn2_kernel<<<128, 256, SMEM_F2>>>(bo, ln2s, ln2b, mask_V, b11,
                                       out, pP2, pG2);

    mlp3_kernel<1><<<NEDGE/64, 256, SMEM64>>>(h_E, pP2, pG2, b12, b13,
                                              nullptr, ln3s, ln3b,
                                              out + (size_t)NTOK * NH, 3);
}

// round 16
// speedup vs baseline: 1.0993x; 1.0122x over previous
#include <cuda_runtime.h>
#include <cuda_fp16.h>
#include <math.h>
#include <stdint.h>

#define NB 2
#define NL 2048
#define NK 48
#define NH 128
#define NTOK (NB*NL)
#define NEDGE (NB*NL*NK)
#define FFH 512

__device__ int   g_idx32[NEDGE];
__device__ float g_h1 [NTOK*NH];
__device__ uint32_t g_h1f16[NTOK*NH/2];
__device__ uint32_t g_hEf16[NEDGE*NH/2];
__device__ uint32_t g_Hhi[NTOK*FFH/2];
__device__ float g_P1 [NTOK*NH];
__device__ float g_G1 [NTOK*NH];
__device__ float g_P2 [NTOK*NH];
__device__ float g_G2 [NTOK*NH];
__device__ float g_partA[NTOK*NH];
__device__ float g_partB[NTOK*NH];
// 18 fp16 matrices [k][n] (128x128), rows padded to 272B -> 2176 uint4 each
__device__ uint4 g_Wb[18*2176];

#define AST 272
#define MST 144
#define M_A   0
#define M_B   17408
#define M_STAT 52224
#define SMEM64 54272
#define SMEMNF 54784

__device__ __forceinline__ float gelu_f(float x) {
    return 0.5f * x * (1.0f + erff(x * 0.7071067811865475f));
}

__device__ __forceinline__ uint32_t smem_u32(const void* p) {
    uint32_t a;
    asm("{ .reg .u64 t; cvta.to.shared.u64 t, %1; cvt.u32.u64 %0, t; }"
        : "=r"(a) : "l"(p));
    return a;
}

__device__ __forceinline__ uint32_t pack_f16(float v0, float v1) {
    __half2 h = __floats2half2_rn(v0, v1);
    return *(uint32_t*)&h;
}

__device__ __forceinline__ void cp16(uint32_t dst, const void* src) {
    asm volatile("cp.async.cg.shared.global [%0], [%1], 16;"
        :: "r"(dst), "l"(src));
}
#define CP_COMMIT() asm volatile("cp.async.commit_group;" ::: "memory")
#define CP_WAIT0()  asm volatile("cp.async.wait_group 0;" ::: "memory")
#define PREF_L2(p)  asm volatile("prefetch.global.L2 [%0];" :: "l"(p))

__device__ __forceinline__ void ldm4(uint32_t r[4], uint32_t a) {
    asm volatile("ldmatrix.sync.aligned.m8n8.x4.shared.b16 {%0,%1,%2,%3}, [%4];"
        : "=r"(r[0]), "=r"(r[1]), "=r"(r[2]), "=r"(r[3]) : "r"(a));
}
__device__ __forceinline__ void ldm4t(uint32_t r[4], uint32_t a) {
    asm volatile("ldmatrix.sync.aligned.m8n8.x4.trans.shared.b16 {%0,%1,%2,%3}, [%4];"
        : "=r"(r[0]), "=r"(r[1]), "=r"(r[2]), "=r"(r[3]) : "r"(a));
}
__device__ __forceinline__ void mma_f16(float c[4], const uint32_t a[4],
                                        uint32_t b0, uint32_t b1) {
    asm volatile(
        "mma.sync.aligned.m16n8k16.row.col.f32.f16.f16.f32 "
        "{%0,%1,%2,%3}, {%4,%5,%6,%7}, {%8,%9}, {%0,%1,%2,%3};"
        : "+f"(c[0]), "+f"(c[1]), "+f"(c[2]), "+f"(c[3])
        : "r"(a[0]), "r"(a[1]), "r"(a[2]), "r"(a[3]), "r"(b0), "r"(b1));
}

// ---------------------------------------------------------------------------
__global__ void convert_kernel(const void* __restrict__ e) {
    __shared__ int s_is64;
    if (threadIdx.x == 0) {
        const int* w = (const int*)e;
        int nz = 0;
        #pragma unroll 8
        for (int i = 1; i < 256; i += 2) nz |= (w[i] != 0);
        s_is64 = (nz == 0);
    }
    __syncthreads();
    int i = blockIdx.x * blockDim.x + threadIdx.x;
    if (i >= NEDGE) return;
    if (s_is64) g_idx32[i] = (int)((const long long*)e)[i];
    else        g_idx32[i] = ((const int*)e)[i];
}

// ---------------------------------------------------------------------------
__global__ void wprep_kernel(const float* W0, const float* W1, const float* W2,
                             const float* W3, const float* W4, const float* W5,
                             const float* Wi, const float* Wo,
                             const float* W1full, const float* W11full) {
    int gid = blockIdx.x * 256 + threadIdx.x;
    if (gid >= 18 * 16384) return;
    int m = gid >> 14, rem = gid & 16383;
    int k = rem >> 7, n = rem & 127;
    float v;
    if (m < 6) {
        const float* W = (m == 0) ? W0 : (m == 1) ? W1 : (m == 2) ? W2
                       : (m == 3) ? W3 : (m == 4) ? W4 : W5;
        v = W[k * 128 + n];
    } else if (m < 10) {
        v = Wi[k * FFH + (m - 6) * 128 + n];
    } else if (m < 14) {
        v = Wo[((m - 10) * 128 + k) * 128 + n];
    } else if (m == 14) {
        v = W1full[k * 128 + n];
    } else if (m == 15) {
        v = W1full[(256 + k) * 128 + n];
    } else if (m == 16) {
        v = W11full[k * 128 + n];
    } else {
        v = W11full[(256 + k) * 128 + n];
    }
    char* basep = (char*)g_Wb + (size_t)m * 34816;
    *(__half*)(basep + (uint32_t)k * 272u + (uint32_t)n * 2u) = __float2half_rn(v);
}

// ---------------------------------------------------------------------------
__device__ __forceinline__ void copyB_async(uint32_t dst, int mat) {
    const uint4* src = &g_Wb[(size_t)mat * 2176];
    #pragma unroll
    for (int i = 0; i < 9; i++) {
        int idx = threadIdx.x + 256*i;
        if (idx < 2176) cp16(dst + idx*16, src + idx);
    }
}

__device__ __forceinline__ void mma_layer64(uint32_t sb, int warpM, int warpN,
                                            int lane, float (&acc)[2][4][4]) {
    #pragma unroll
    for (int m = 0; m < 2; m++)
        #pragma unroll
        for (int j = 0; j < 4; j++)
            #pragma unroll
            for (int c = 0; c < 4; c++) acc[m][j][c] = 0.0f;

    uint32_t aA = sb + M_A + (uint32_t)(warpM*32 + (lane & 15))*AST
                + (uint32_t)(lane >> 4)*16;
    uint32_t bB = sb + M_B + (uint32_t)(lane & 15)*AST
                + (uint32_t)(warpN*4 + (lane >> 4))*16;

    #pragma unroll
    for (int ks = 0; ks < 8; ks++) {
        uint32_t ah0[4], ah1[4];
        ldm4(ah0, aA + ks*32);
        ldm4(ah1, aA + ks*32 + 16*AST);
        #pragma unroll
        for (int ng = 0; ng < 2; ng++) {
            uint32_t bh[4];
            ldm4t(bh, bB + ks*16*AST + ng*32);
            mma_f16(acc[0][2*ng],   ah0, bh[0], bh[1]);
            mma_f16(acc[1][2*ng],   ah1, bh[0], bh[1]);
            mma_f16(acc[0][2*ng+1], ah0, bh[2], bh[3]);
            mma_f16(acc[1][2*ng+1], ah1, bh[2], bh[3]);
        }
    }
}

__device__ __forceinline__ void loadA64(char* sm, const float* src, int tid) {
    for (int idx = tid; idx < 64*64; idx += 256) {
        int r = idx >> 6, cp = idx & 63;
        float2 x = *(const float2*)&src[(size_t)r*NH + cp*2];
        *(uint32_t*)(sm + M_A + r*AST + cp*4) = pack_f16(x.x, x.y);
    }
}

__device__ __forceinline__ void loadA64_cached(uint32_t sb, const uint32_t* cache,
                                               size_t row0, int tid) {
    #pragma unroll
    for (int i = 0; i < 4; i++) {
        int idx = tid + 256*i;
        int r = idx >> 4, q4 = (idx & 15) * 4;
        cp16(sb + M_A + r*AST + q4*4, &cache[(row0 + r)*64 + q4]);
    }
}

// ---------------------------------------------------------------------------
// tokenPG fused: P = A@W14 + b ; G = A@W15. grid 64.
// ---------------------------------------------------------------------------
__global__ void __launch_bounds__(256, 3) tokenPG_kernel(
    const float* __restrict__ A, const float* __restrict__ bias,
    float* __restrict__ P, float* __restrict__ G)
{
    extern __shared__ char sm[];
    uint32_t sb = smem_u32(sm);
    int tid = threadIdx.x;
    int wid = tid >> 5, lane = tid & 31;
    int warpM = wid & 1, warpN = wid >> 1;
    int qr = lane >> 2, qc = lane & 3;
    int bl0 = blockIdx.x * 64;
    int cBase = warpN*32 + 2*qc;

    copyB_async(sb + M_B, 14);
    CP_COMMIT();
    loadA64(sm, A + (size_t)bl0*NH, tid);
    CP_WAIT0();
    __syncthreads();

    float acc[2][4][4];
    mma_layer64(sb, warpM, warpN, lane, acc);
    __syncthreads();
    copyB_async(sb + M_B, 15);
    CP_COMMIT();

    #pragma unroll
    for (int mf = 0; mf < 2; mf++)
        #pragma unroll
        for (int j = 0; j < 4; j++) {
            int C = cBase + j*8;
            float2 bv = *(const float2*)&bias[C];
            #pragma unroll
            for (int h = 0; h < 2; h++) {
                int R = warpM*32 + mf*16 + h*8 + qr;
                float2 o2;
                o2.x = acc[mf][j][2*h+0] + bv.x;
                o2.y = acc[mf][j][2*h+1] + bv.y;
                *(float2*)&P[(size_t)(bl0 + R)*NH + C] = o2;
            }
        }
    CP_WAIT0();
    __syncthreads();

    mma_layer64(sb, warpM, warpN, lane, acc);
    #pragma unroll
    for (int mf = 0; mf < 2; mf++)
        #pragma unroll
        for (int j = 0; j < 4; j++) {
            int C = cBase + j*8;
            #pragma unroll
            for (int h = 0; h < 2; h++) {
                int R = warpM*32 + mf*16 + h*8 + qr;
                float2 o2;
                o2.x = acc[mf][j][2*h+0];
                o2.y = acc[mf][j][2*h+1];
                *(float2*)&G[(size_t)(bl0 + R)*NH + C] = o2;
            }
        }
}

// ---------------------------------------------------------------------------
// mlp3: 64 edge rows per CTA, occ=4. MODE 0 = node (2 layers + mma GEMV
// masked row-sum; writes hE fp16 cache). MODE 1 = edge (3 layers + LN3).
// ---------------------------------------------------------------------------
template<int MODE>
__global__ void __launch_bounds__(256, 4) mlp3_kernel(
    const float* __restrict__ hE,
    const float* __restrict__ P, const float* __restrict__ G,
    const float* __restrict__ bias2, const float* __restrict__ bias3,
    const float* __restrict__ mask_attend,
    const float* __restrict__ ln3s, const float* __restrict__ ln3b,
    float* __restrict__ out_hE, int matBase)
{
    extern __shared__ char sm[];
    uint32_t sb = smem_u32(sm);

    int tid = threadIdx.x;
    int wid = tid >> 5, lane = tid & 31;
    int warpM = wid & 1, warpN = wid >> 1;
    int qr = lane >> 2, qc = lane & 3;
    int e0 = blockIdx.x * 64;
    int cBase = warpN*32 + 2*qc;

    int Row[2][2];
    #pragma unroll
    for (int mf = 0; mf < 2; mf++)
        #pragma unroll
        for (int h = 0; h < 2; h++)
            Row[mf][h] = warpM*32 + mf*16 + h*8 + qr;

    copyB_async(sb + M_B, matBase + 0);
    if (MODE == 0) {
        CP_COMMIT();
        for (int idx = tid; idx < 64*64; idx += 256) {
            int r = idx >> 6, cp = idx & 63;
            float2 x = *(const float2*)&hE[(size_t)(e0 + r)*NH + cp*2];
            uint32_t u = pack_f16(x.x, x.y);
            *(uint32_t*)(sm + M_A + r*AST + cp*4) = u;
            g_hEf16[(size_t)(e0 + r)*64 + cp] = u;
        }
    } else {
        loadA64_cached(sb, g_hEf16, (size_t)e0, tid);
        CP_COMMIT();
    }
    // L2 prefetch of P/G gather rows for epilogue 1
    {
        int r = tid >> 2, ln = tid & 3;
        int e = e0 + r;
        int tok = e / 48;
        int batch = (e >= NL*NK) ? 1 : 0;
        PREF_L2(&P[(size_t)tok*NH + ln*32]);
        PREF_L2(&G[(size_t)(batch*NL + g_idx32[e])*NH + ln*32]);
    }
    CP_WAIT0();
    __syncthreads();

    float acc[2][4][4];

    // ---- layer 1 ----
    mma_layer64(sb, warpM, warpN, lane, acc);
    __syncthreads();
    copyB_async(sb + M_B, matBase + 1);
    CP_COMMIT();
    {
        const float* Pr[2][2];
        const float* Gr[2][2];
        #pragma unroll
        for (int mf = 0; mf < 2; mf++)
            #pragma unroll
            for (int h = 0; h < 2; h++) {
                int e = e0 + Row[mf][h];
                int tok = e / 48;
                int batch = (e >= NL*NK) ? 1 : 0;
                Pr[mf][h] = P + (size_t)tok * NH;
                Gr[mf][h] = G + (size_t)(batch*NL + g_idx32[e]) * NH;
            }
        #pragma unroll
        for (int mf = 0; mf < 2; mf++)
            #pragma unroll
            for (int j = 0; j < 4; j++) {
                int C = cBase + j*8;
                #pragma unroll
                for (int h = 0; h < 2; h++) {
                    float2 pv = *(const float2*)&Pr[mf][h][C];
                    float2 gv = *(const float2*)&Gr[mf][h][C];
                    float v0 = gelu_f(acc[mf][j][2*h+0] + pv.x + gv.x);
                    float v1 = gelu_f(acc[mf][j][2*h+1] + pv.y + gv.y);
                    int R = Row[mf][h];
                    *(uint32_t*)(sm + M_A + R*AST + C*2) = pack_f16(v0, v1);
                }
            }
    }
    CP_WAIT0();
    __syncthreads();

    // ---- layer 2 ----
    mma_layer64(sb, warpM, warpN, lane, acc);
    __syncthreads();

    if (MODE == 0) {
        // Zm = gelu(acc + b2)*mask -> fp16 A region (B dead after layer 2)
        #pragma unroll
        for (int mf = 0; mf < 2; mf++)
            #pragma unroll
            for (int h = 0; h < 2; h++) {
                int R = Row[mf][h];
                float mk = mask_attend[e0 + R];
                #pragma unroll
                for (int j = 0; j < 4; j++) {
                    int C = cBase + j*8;
                    float2 bv = *(const float2*)&bias2[C];
                    float v0 = gelu_f(acc[mf][j][2*h+0] + bv.x) * mk;
                    float v1 = gelu_f(acc[mf][j][2*h+1] + bv.y) * mk;
                    *(uint32_t*)(sm + M_A + R*AST + C*2) = pack_f16(v0, v1);
                }
            }
        // mask ones-tile [16 x 64] fp16 in B region (stride MST); row r<2 only
        int t0 = e0 / 48;
        for (int i = tid; i < 16*64; i += 256) {
            int r = i >> 6, el = i & 63;
            float mval = 0.0f;
            if (r < 2 && ((e0 + el) / 48 - t0) == r)
                mval = 1.0f;
            *(__half*)(sm + M_B + r*MST + el*2) = __float2half_rn(mval);
        }
        __syncthreads();
        // GEMV: S[2][128] = maskT(2x64) @ Zm(64x128) via mma
        if (warpM == 0) {
            float sacc[4][4];
            #pragma unroll
            for (int j = 0; j < 4; j++)
                #pragma unroll
                for (int c = 0; c < 4; c++) sacc[j][c] = 0.0f;
            uint32_t aM = sb + M_B + (uint32_t)(lane & 15)*MST
                        + (uint32_t)(lane >> 4)*16;
            uint32_t bZ = sb + M_A + (uint32_t)(lane & 15)*AST
                        + (uint32_t)(warpN*4 + (lane >> 4))*16;
            #pragma unroll
            for (int kc = 0; kc < 4; kc++) {
                uint32_t am[4];
                ldm4(am, aM + kc*32);
                #pragma unroll
                for (int ng = 0; ng < 2; ng++) {
                    uint32_t bh[4];
                    ldm4t(bh, bZ + kc*16*AST + ng*32);
                    mma_f16(sacc[2*ng],   am, bh[0], bh[1]);
                    mma_f16(sacc[2*ng+1], am, bh[2], bh[3]);
                }
            }
            if (qr < 2) {
                int t = t0 + qr;
                float* dst;
                if (qr == 0)
                    dst = (t0*48 >= e0) ? &g_partA[(size_t)t*NH]
                                        : &g_partB[(size_t)t*NH];
                else
                    dst = &g_partA[(size_t)t*NH];
                #pragma unroll
                for (int j = 0; j < 4; j++) {
                    int col = warpN*32 + j*8 + qc*2;
                    *(float2*)&dst[col] = make_float2(sacc[j][0], sacc[j][1]);
                }
            }
        }
        return;
    }

    // ---- edge path: layer-2 epilogue, layer 3, LN3 ----
    copyB_async(sb + M_B, matBase + 2);
    CP_COMMIT();
    #pragma unroll
    for (int mf = 0; mf < 2; mf++)
        #pragma unroll
        for (int j = 0; j < 4; j++) {
            int C = cBase + j*8;
            float2 bv = *(const float2*)&bias2[C];
            #pragma unroll
            for (int h = 0; h < 2; h++) {
                float v0 = gelu_f(acc[mf][j][2*h+0] + bv.x);
                float v1 = gelu_f(acc[mf][j][2*h+1] + bv.y);
                int R = Row[mf][h];
                *(uint32_t*)(sm + M_A + R*AST + C*2) = pack_f16(v0, v1);
            }
        }
    // L2 prefetch residual hE rows for LN3 epilogue
    {
        int r = tid >> 2, ln = tid & 3;
        PREF_L2(&hE[(size_t)(e0 + r)*NH + ln*32]);
    }
    CP_WAIT0();
    __syncthreads();

    mma_layer64(sb, warpM, warpN, lane, acc);
    __syncthreads();

    float* stats = (float*)(sm + M_STAT);
    float s1[2][2], s2[2][2];
    #pragma unroll
    for (int mf = 0; mf < 2; mf++)
        #pragma unroll
        for (int h = 0; h < 2; h++) { s1[mf][h] = 0.f; s2[mf][h] = 0.f; }
    #pragma unroll
    for (int mf = 0; mf < 2; mf++)
        #pragma unroll
        for (int j = 0; j < 4; j++) {
            int C = cBase + j*8;
            float2 bv = *(const float2*)&bias3[C];
            #pragma unroll
            for (int h = 0; h < 2; h++) {
                int R = Row[mf][h];
                float2 he = *(const float2*)&hE[(size_t)(e0 + R)*NH + C];
                float v0 = acc[mf][j][2*h+0] + bv.x + he.x;
                float v1 = acc[mf][j][2*h+1] + bv.y + he.y;
                acc[mf][j][2*h+0] = v0;
                acc[mf][j][2*h+1] = v1;
                s1[mf][h] += v0 + v1;
                s2[mf][h] += v0*v0 + v1*v1;
            }
        }
    #pragma unroll
    for (int mf = 0; mf < 2; mf++)
        #pragma unroll
        for (int h = 0; h < 2; h++) {
            #pragma unroll
            for (int o = 1; o < 4; o <<= 1) {
                s1[mf][h] += __shfl_xor_sync(0xffffffffu, s1[mf][h], o);
                s2[mf][h] += __shfl_xor_sync(0xffffffffu, s2[mf][h], o);
            }
            if (qc == 0) {
                stats[(warpN*64 + Row[mf][h])*2 + 0] = s1[mf][h];
                stats[(warpN*64 + Row[mf][h])*2 + 1] = s2[mf][h];
            }
        }
    __syncthreads();
    #pragma unroll
    for (int mf = 0; mf < 2; mf++)
        #pragma unroll
        for (int h = 0; h < 2; h++) {
            int R = Row[mf][h];
            float S1 = 0.f, S2 = 0.f;
            #pragma unroll
            for (int g = 0; g < 4; g++) {
                S1 += stats[(g*64 + R)*2 + 0];
                S2 += stats[(g*64 + R)*2 + 1];
            }
            float mu = S1 * (1.0f / NH);
            float var = S2 * (1.0f / NH) - mu * mu;
            float rinv = rsqrtf(var + 1e-5f);
            #pragma unroll
            for (int j = 0; j < 4; j++) {
                int C = cBase + j*8;
                float2 gs = *(const float2*)&ln3s[C];
                float2 gb = *(const float2*)&ln3b[C];
                float2 o2;
                o2.x = (acc[mf][j][2*h+0] - mu) * rinv * gs.x + gb.x;
                o2.y = (acc[mf][j][2*h+1] - mu) * rinv * gs.y + gb.y;
                *(float2*)&out_hE[(size_t)(e0 + R)*NH + C] = o2;
            }
        }
}

// ---------------------------------------------------------------------------
// nodeFin: dh = S@W3 + (Σmask)*b3 ; h1 = LN1(hV + dh/30). 64 tokens/CTA.
// ---------------------------------------------------------------------------
__global__ void __launch_bounds__(256) nodeFin_kernel(
    const float* __restrict__ hV, const float* __restrict__ b3,
    const float* __restrict__ mask_attend,
    const float* __restrict__ ln1s, const float* __restrict__ ln1b)
{
    extern __shared__ char sm[];
    uint32_t sb = smem_u32(sm);
    int tid = threadIdx.x;
    int wid = tid >> 5, lane = tid & 31;
    int warpM = wid & 1, warpN = wid >> 1;
    int qr = lane >> 2, qc = lane & 3;
    int bl0 = blockIdx.x * 64;
    int cBase = warpN*32 + 2*qc;

    copyB_async(sb + M_B, 2);   // W3
    CP_COMMIT();
    for (int idx = tid; idx < 64*64; idx += 256) {
        int r = idx >> 6, cp = idx & 63;
        int t = bl0 + r;
        float2 x = *(const float2*)&g_partA[(size_t)t*NH + cp*2];
        int s0 = t * 48;
        if (s0 / 64 != (s0 + 47) / 64) {
            float2 y = *(const float2*)&g_partB[(size_t)t*NH + cp*2];
            x.x += y.x; x.y += y.y;
        }
        *(uint32_t*)(sm + M_A + r*AST + cp*4) = pack_f16(x.x, x.y);
    }
    CP_WAIT0();
    __syncthreads();

    float acc[2][4][4];
    mma_layer64(sb, warpM, warpN, lane, acc);

    float* stats = (float*)(sm + M_STAT);
    float* msum  = (float*)(sm + M_STAT + 2048);
    if (tid < 64) {
        int t = bl0 + tid;
        float s = 0.0f;
        #pragma unroll 4
        for (int k = 0; k < NK; k += 4) {
            float4 m4 = *(const float4*)&mask_attend[t*NK + k];
            s += m4.x + m4.y + m4.z + m4.w;
        }
        msum[tid] = s;
    }
    __syncthreads();

    int Row[2][2];
    #pragma unroll
    for (int mf = 0; mf < 2; mf++)
        #pragma unroll
        for (int h = 0; h < 2; h++)
            Row[mf][h] = warpM*32 + mf*16 + h*8 + qr;

    float s1[2][2], s2[2][2];
    #pragma unroll
    for (int mf = 0; mf < 2; mf++)
        #pragma unroll
        for (int h = 0; h < 2; h++) { s1[mf][h] = 0.f; s2[mf][h] = 0.f; }

    #pragma unroll
    for (int mf = 0; mf < 2; mf++)
        #pragma unroll
        for (int j = 0; j < 4; j++) {
            int C = cBase + j*8;
            float2 bv = *(const float2*)&b3[C];
            #pragma unroll
            for (int h = 0; h < 2; h++) {
                int R = Row[mf][h];
                int t = bl0 + R;
                float ms = msum[R];
                float2 hv = *(const float2*)&hV[(size_t)t*NH + C];
                float v0 = hv.x + (acc[mf][j][2*h+0] + ms*bv.x) * (1.0f/30.0f);
                float v1 = hv.y + (acc[mf][j][2*h+1] + ms*bv.y) * (1.0f/30.0f);
                acc[mf][j][2*h+0] = v0;
                acc[mf][j][2*h+1] = v1;
                s1[mf][h] += v0 + v1;
                s2[mf][h] += v0*v0 + v1*v1;
            }
        }
    #pragma unroll
    for (int mf = 0; mf < 2; mf++)
        #pragma unroll
        for (int h = 0; h < 2; h++) {
            #pragma unroll
            for (int o = 1; o < 4; o <<= 1) {
                s1[mf][h] += __shfl_xor_sync(0xffffffffu, s1[mf][h], o);
                s2[mf][h] += __shfl_xor_sync(0xffffffffu, s2[mf][h], o);
            }
            if (qc == 0) {
                stats[(warpN*64 + Row[mf][h])*2 + 0] = s1[mf][h];
                stats[(warpN*64 + Row[mf][h])*2 + 1] = s2[mf][h];
            }
        }
    __syncthreads();
    #pragma unroll
    for (int mf = 0; mf < 2; mf++)
        #pragma unroll
        for (int h = 0; h < 2; h++) {
            int R = Row[mf][h];
            float S1 = 0.f, S2 = 0.f;
            #pragma unroll
            for (int g = 0; g < 4; g++) {
                S1 += stats[(g*64 + R)*2 + 0];
                S2 += stats[(g*64 + R)*2 + 1];
            }
            float mu = S1 * (1.0f / NH);
            float var = S2 * (1.0f / NH) - mu * mu;
            float rinv = rsqrtf(var + 1e-5f);
            #pragma unroll
            for (int j = 0; j < 4; j++) {
                int C = cBase + j*8;
                float2 gs = *(const float2*)&ln1s[C];
                float2 gb = *(const float2*)&ln1b[C];
                float2 o2;
                o2.x = (acc[mf][j][2*h+0] - mu) * rinv * gs.x + gb.x;
                o2.y = (acc[mf][j][2*h+1] - mu) * rinv * gs.y + gb.y;
                *(float2*)&g_h1[(size_t)(bl0 + R)*NH + C] = o2;
                g_h1f16[(size_t)(bl0 + R)*64 + (C >> 1)] = pack_f16(o2.x, o2.y);
            }
        }
}

// ---------------------------------------------------------------------------
// ffn1 (mma): H tile [64tok x 128col] = gelu(h1 @ Wi + bi), fp16 out.
// grid (64, 4).
// ---------------------------------------------------------------------------
__global__ void __launch_bounds__(256, 3) ffn1_kernel(const float* __restrict__ bi)
{
    extern __shared__ char sm[];
    uint32_t sb = smem_u32(sm);
    int tid = threadIdx.x;
    int wid = tid >> 5, lane = tid & 31;
    int warpM = wid & 1, warpN = wid >> 1;
    int qr = lane >> 2, qc = lane & 3;
    int bl0 = blockIdx.x * 64;
    int nb  = blockIdx.y * 128;
    int cBase = warpN*32 + 2*qc;

    copyB_async(sb + M_B, 6 + blockIdx.y);
    loadA64_cached(sb, g_h1f16, (size_t)bl0, tid);
    CP_COMMIT();
    CP_WAIT0();
    __syncthreads();

    float acc[2][4][4];
    mma_layer64(sb, warpM, warpN, lane, acc);

    #pragma unroll
    for (int mf = 0; mf < 2; mf++)
        #pragma unroll
        for (int j = 0; j < 4; j++) {
            int C = cBase + j*8;
            float2 bv = *(const float2*)&bi[nb + C];
            #pragma unroll
            for (int h = 0; h < 2; h++) {
                int R = warpM*32 + mf*16 + h*8 + qr;
                float v0 = gelu_f(acc[mf][j][2*h+0] + bv.x);
                float v1 = gelu_f(acc[mf][j][2*h+1] + bv.y);
                uint32_t gi = ((uint32_t)(bl0 + R)*FFH + nb + C) >> 1;
                g_Hhi[gi] = pack_f16(v0, v1);
            }
        }
}

// ---------------------------------------------------------------------------
// ffn2 (mma): hV2 = LN2(h1 + H @ Wo + bo) * mask_V, then fused
// P2 = hV2@W11P + b11, G2 = hV2@W11G. 32 tok/CTA, grid 128.
// ---------------------------------------------------------------------------
#define F2_A   0
#define F2_B   8704
#define F2_STAT 43520
#define SMEM_F2 45568

__device__ __forceinline__ void mma_32(uint32_t sb, int warpM, int warpN,
                                       int lane, float (&acc)[4][4]) {
    #pragma unroll
    for (int j = 0; j < 4; j++)
        #pragma unroll
        for (int c = 0; c < 4; c++) acc[j][c] = 0.0f;
    uint32_t aA = sb + F2_A + (uint32_t)(warpM*16 + (lane & 15))*AST
                + (uint32_t)(lane >> 4)*16;
    uint32_t bB = sb + F2_B + (uint32_t)(lane & 15)*AST
                + (uint32_t)(warpN*4 + (lane >> 4))*16;
    #pragma unroll
    for (int ks = 0; ks < 8; ks++) {
        uint32_t ah[4];
        ldm4(ah, aA + ks*32);
        #pragma unroll
        for (int ng = 0; ng < 2; ng++) {
            uint32_t bh[4];
            ldm4t(bh, bB + ks*16*AST + ng*32);
            mma_f16(acc[2*ng],   ah, bh[0], bh[1]);
            mma_f16(acc[2*ng+1], ah, bh[2], bh[3]);
        }
    }
}

__global__ void __launch_bounds__(256) ffn2_kernel(
    const float* __restrict__ bo,
    const float* __restrict__ ln2s, const float* __restrict__ ln2b,
    const float* __restrict__ mask_V, const float* __restrict__ b11,
    float* __restrict__ out_hV, float* __restrict__ P2, float* __restrict__ G2)
{
    extern __shared__ char sm[];
    uint32_t sb = smem_u32(sm);
    int tid = threadIdx.x;
    int wid = tid >> 5, lane = tid & 31;
    int warpM = wid & 1, warpN = wid >> 1;
    int qr = lane >> 2, qc = lane & 3;
    int bl0 = blockIdx.x * 32;
    int cBase = warpN*32 + 2*qc;

    float acc[4][4];
    #pragma unroll
    for (int j = 0; j < 4; j++)
        #pragma unroll
        for (int c = 0; c < 4; c++) acc[j][c] = 0.0f;

    for (int ch = 0; ch < 4; ch++) {
        {
            int idx = tid;
            #pragma unroll
            for (int i = 0; i < 2; i++) {
                int r = idx >> 4, q4 = (idx & 15) * 4;
                uint32_t gi = (uint32_t)(bl0 + r)*256 + ch*64 + q4;
                cp16(sb + F2_A + r*AST + q4*4, &g_Hhi[gi]);
                idx += 256;
            }
        }
        copyB_async(sb + F2_B, 10 + ch);
        CP_COMMIT();
        CP_WAIT0();
        __syncthreads();

        uint32_t aA = sb + F2_A + (uint32_t)(warpM*16 + (lane & 15))*AST
                    + (uint32_t)(lane >> 4)*16;
        uint32_t bB = sb + F2_B + (uint32_t)(lane & 15)*AST
                    + (uint32_t)(warpN*64 + (lane >> 4)*16);

        #pragma unroll
        for (int ks = 0; ks < 8; ks++) {
            uint32_t ah[4];
            ldm4(ah, aA + ks*32);
            #pragma unroll
            for (int ng = 0; ng < 2; ng++) {
                uint32_t bh[4];
                ldm4t(bh, bB + ks*16*AST + ng*32);
                mma_f16(acc[2*ng],   ah, bh[0], bh[1]);
                mma_f16(acc[2*ng+1], ah, bh[2], bh[3]);
            }
        }
        __syncthreads();
    }

    float* stats = (float*)(sm + F2_STAT);
    float s1[2], s2[2];
    #pragma unroll
    for (int h = 0; h < 2; h++) { s1[h] = 0.f; s2[h] = 0.f; }
    #pragma unroll
    for (int j = 0; j < 4; j++) {
        int C = cBase + j*8;
        float2 bv = *(const float2*)&bo[C];
        #pragma unroll
        for (int h = 0; h < 2; h++) {
            int R = warpM*16 + h*8 + qr;
            float2 hv = *(const float2*)&g_h1[(size_t)(bl0 + R)*NH + C];
            float v0 = acc[j][2*h+0] + bv.x + hv.x;
            float v1 = acc[j][2*h+1] + bv.y + hv.y;
            acc[j][2*h+0] = v0;
            acc[j][2*h+1] = v1;
            s1[h] += v0 + v1;
            s2[h] += v0*v0 + v1*v1;
        }
    }
    #pragma unroll
    for (int h = 0; h < 2; h++) {
        #pragma unroll
        for (int o = 1; o < 4; o <<= 1) {
            s1[h] += __shfl_xor_sync(0xffffffffu, s1[h], o);
            s2[h] += __shfl_xor_sync(0xffffffffu, s2[h], o);
        }
        if (qc == 0) {
            int R = warpM*16 + h*8 + qr;
            stats[(warpN*32 + R)*2 + 0] = s1[h];
            stats[(warpN*32 + R)*2 + 1] = s2[h];
        }
    }
    __syncthreads();
    #pragma unroll
    for (int h = 0; h < 2; h++) {
        int R = warpM*16 + h*8 + qr;
        float S1 = 0.f, S2 = 0.f;
        #pragma unroll
        for (int g = 0; g < 4; g++) {
            S1 += stats[(g*32 + R)*2 + 0];
            S2 += stats[(g*32 + R)*2 + 1];
        }
        float mu = S1 * (1.0f / NH);
        float var = S2 * (1.0f / NH) - mu * mu;
        float rinv = rsqrtf(var + 1e-5f);
        int token = bl0 + R;
        float mk = mask_V[token];
        #pragma unroll
        for (int j = 0; j < 4; j++) {
            int C = cBase + j*8;
            float2 gs = *(const float2*)&ln2s[C];
            float2 gb = *(const float2*)&ln2b[C];
            float2 o2;
            o2.x = ((acc[j][2*h+0] - mu) * rinv * gs.x + gb.x) * mk;
            o2.y = ((acc[j][2*h+1] - mu) * rinv * gs.y + gb.y) * mk;
            *(float2*)&out_hV[(size_t)token*NH + C] = o2;
            *(uint32_t*)(sm + F2_A + R*AST + C*2) = pack_f16(o2.x, o2.y);
        }
    }
    __syncthreads();

    copyB_async(sb + F2_B, 16);
    CP_COMMIT();
    CP_WAIT0();
    __syncthreads();
    float acc2[4][4];
    mma_32(sb, warpM, warpN, lane, acc2);
    #pragma unroll
    for (int j = 0; j < 4; j++) {
        int C = cBase + j*8;
        float2 bv = *(const float2*)&b11[C];
        #pragma unroll
        for (int h = 0; h < 2; h++) {
            int R = warpM*16 + h*8 + qr;
            float2 o2;
            o2.x = acc2[j][2*h+0] + bv.x;
            o2.y = acc2[j][2*h+1] + bv.y;
            *(float2*)&P2[(size_t)(bl0 + R)*NH + C] = o2;
        }
    }
    __syncthreads();

    copyB_async(sb + F2_B, 17);
    CP_COMMIT();
    CP_WAIT0();
    __syncthreads();
    mma_32(sb, warpM, warpN, lane, acc2);
    #pragma unroll
    for (int j = 0; j < 4; j++) {
        int C = cBase + j*8;
        #pragma unroll
        for (int h = 0; h < 2; h++) {
            int R = warpM*16 + h*8 + qr;
            float2 o2;
            o2.x = acc2[j][2*h+0];
            o2.y = acc2[j][2*h+1];
            *(float2*)&G2[(size_t)(bl0 + R)*NH + C] = o2;
        }
    }
}

// ---------------------------------------------------------------------------

extern "C" void kernel_launch(void* const* d_in, const int* in_sizes, int n_in,
                              void* d_out, int out_size)
{
    const float* h_V         = (const float*)d_in[0];
    const float* h_E         = (const float*)d_in[1];
    const void*  E_idx       =               d_in[2];
    const float* mask_V      = (const float*)d_in[3];
    const float* mask_attend = (const float*)d_in[4];
    const float* W1  = (const float*)d_in[5],  *b1  = (const float*)d_in[6];
    const float* W2  = (const float*)d_in[7],  *b2  = (const float*)d_in[8];
    const float* W3  = (const float*)d_in[9],  *b3  = (const float*)d_in[10];
    const float* W11 = (const float*)d_in[11], *b11 = (const float*)d_in[12];
    const float* W12 = (const float*)d_in[13], *b12 = (const float*)d_in[14];
    const float* W13 = (const float*)d_in[15], *b13 = (const float*)d_in[16];
    const float* Wi  = (const float*)d_in[17], *bi  = (const float*)d_in[18];
    const float* Wo  = (const float*)d_in[19], *bo  = (const float*)d_in[20];
    const float* ln1s = (const float*)d_in[21], *ln1b = (const float*)d_in[22];
    const float* ln2s = (const float*)d_in[23], *ln2b = (const float*)d_in[24];
    const float* ln3s = (const float*)d_in[25], *ln3b = (const float*)d_in[26];
    float* out = (float*)d_out;

    float *pP1, *pG1, *pP2, *pG2;
    cudaGetSymbolAddress((void**)&pP1,  g_P1);
    cudaGetSymbolAddress((void**)&pG1,  g_G1);
    cudaGetSymbolAddress((void**)&pP2,  g_P2);
    cudaGetSymbolAddress((void**)&pG2,  g_G2);

    cudaFuncSetAttribute(tokenPG_kernel, cudaFuncAttributeMaxDynamicSharedMemorySize, SMEM64);
    cudaFuncSetAttribute(ffn1_kernel,  cudaFuncAttributeMaxDynamicSharedMemorySize, SMEM64);
    cudaFuncSetAttribute(ffn2_kernel,  cudaFuncAttributeMaxDynamicSharedMemorySize, SMEM_F2);
    cudaFuncSetAttribute(nodeFin_kernel, cudaFuncAttributeMaxDynamicSharedMemorySize, SMEMNF);
    cudaFuncSetAttribute(mlp3_kernel<0>, cudaFuncAttributeMaxDynamicSharedMemorySize, SMEM64);
    cudaFuncSetAttribute(mlp3_kernel<1>, cudaFuncAttributeMaxDynamicSharedMemorySize, SMEM64);

    convert_kernel<<<(NEDGE + 255) / 256, 256>>>(E_idx);

    wprep_kernel<<<(18*16384 + 255)/256, 256>>>(W1 + 128*NH, W2, W3,
                                                W11 + 128*NH, W12, W13, Wi, Wo,
                                                W1, W11);

    tokenPG_kernel<<<64, 256, SMEM64>>>(h_V, b1, pP1, pG1);

    mlp3_kernel<0><<<NEDGE/64, 256, SMEM64>>>(h_E, pP1, pG1, b2, nullptr,
                                              mask_attend, nullptr, nullptr,
                                              nullptr, 0);
    nodeFin_kernel<<<64, 256, SMEMNF>>>(h_V, b3, mask_attend, ln1s, ln1b);

    ffn1_kernel<<<dim3(64, 4), 256, SMEM64>>>(bi);
    ffn2_kernel<<<128, 256, SMEM_F2>>>(bo, ln2s, ln2b, mask_V, b11,
                                       out, pP2, pG2);

    mlp3_kernel<1><<<NEDGE/64, 256, SMEM64>>>(h_E, pP2, pG2, b12, b13,
                                              nullptr, ln3s, ln3b,
                                              out + (size_t)NTOK * NH, 3);
}

// round 17
// speedup vs baseline: 1.2474x; 1.1348x over previous
#include <cuda_runtime.h>
#include <cuda_fp16.h>
#include <math.h>
#include <stdint.h>

#define NB 2
#define NL 2048
#define NK 48
#define NH 128
#define NTOK (NB*NL)
#define NEDGE (NB*NL*NK)
#define FFH 512

__device__ int   g_idx32[NEDGE];
__device__ float g_h1 [NTOK*NH];
__device__ uint32_t g_h1f16[NTOK*NH/2];
__device__ uint32_t g_hEf16[NEDGE*NH/2];
__device__ uint32_t g_Hhi[NTOK*FFH/2];
__device__ float g_P1 [NTOK*NH];
__device__ float g_G1 [NTOK*NH];
__device__ float g_P2 [NTOK*NH];
__device__ float g_G2 [NTOK*NH];
__device__ float g_partA[NTOK*NH];
__device__ float g_partB[NTOK*NH];
// 18 fp16 matrices [k][n] (128x128), rows padded to 272B -> 2176 uint4 each
__device__ uint4 g_Wb[18*2176];

#define AST 272
#define MST 144
#define M_A   0
#define M_B   17408
#define M_STAT 52224
#define SMEM64 54272
#define SMEMNF 54784

// fast gelu: tanh approximation in sigmoid form, branch-free.
// g = x * (1 - 1/(e+1)), e = exp(1.5957691*x + 0.0713548*x^3)
__device__ __forceinline__ float gelu_f(float x) {
    float x2 = x * x;
    float y  = x * fmaf(0.0713548162f, x2, 1.5957691216f);
    float e  = __expf(y);
    return x - x * __fdividef(1.0f, e + 1.0f);
}

__device__ __forceinline__ uint32_t smem_u32(const void* p) {
    uint32_t a;
    asm("{ .reg .u64 t; cvta.to.shared.u64 t, %1; cvt.u32.u64 %0, t; }"
        : "=r"(a) : "l"(p));
    return a;
}

__device__ __forceinline__ uint32_t pack_f16(float v0, float v1) {
    __half2 h = __floats2half2_rn(v0, v1);
    return *(uint32_t*)&h;
}

__device__ __forceinline__ void cp16(uint32_t dst, const void* src) {
    asm volatile("cp.async.cg.shared.global [%0], [%1], 16;"
        :: "r"(dst), "l"(src));
}
#define CP_COMMIT() asm volatile("cp.async.commit_group;" ::: "memory")
#define CP_WAIT0()  asm volatile("cp.async.wait_group 0;" ::: "memory")
#define PREF_L2(p)  asm volatile("prefetch.global.L2 [%0];" :: "l"(p))

__device__ __forceinline__ void ldm4(uint32_t r[4], uint32_t a) {
    asm volatile("ldmatrix.sync.aligned.m8n8.x4.shared.b16 {%0,%1,%2,%3}, [%4];"
        : "=r"(r[0]), "=r"(r[1]), "=r"(r[2]), "=r"(r[3]) : "r"(a));
}
__device__ __forceinline__ void ldm4t(uint32_t r[4], uint32_t a) {
    asm volatile("ldmatrix.sync.aligned.m8n8.x4.trans.shared.b16 {%0,%1,%2,%3}, [%4];"
        : "=r"(r[0]), "=r"(r[1]), "=r"(r[2]), "=r"(r[3]) : "r"(a));
}
__device__ __forceinline__ void mma_f16(float c[4], const uint32_t a[4],
                                        uint32_t b0, uint32_t b1) {
    asm volatile(
        "mma.sync.aligned.m16n8k16.row.col.f32.f16.f16.f32 "
        "{%0,%1,%2,%3}, {%4,%5,%6,%7}, {%8,%9}, {%0,%1,%2,%3};"
        : "+f"(c[0]), "+f"(c[1]), "+f"(c[2]), "+f"(c[3])
        : "r"(a[0]), "r"(a[1]), "r"(a[2]), "r"(a[3]), "r"(b0), "r"(b1));
}

// ---------------------------------------------------------------------------
__global__ void convert_kernel(const void* __restrict__ e) {
    __shared__ int s_is64;
    if (threadIdx.x == 0) {
        const int* w = (const int*)e;
        int nz = 0;
        #pragma unroll 8
        for (int i = 1; i < 256; i += 2) nz |= (w[i] != 0);
        s_is64 = (nz == 0);
    }
    __syncthreads();
    int i = blockIdx.x * blockDim.x + threadIdx.x;
    if (i >= NEDGE) return;
    if (s_is64) g_idx32[i] = (int)((const long long*)e)[i];
    else        g_idx32[i] = ((const int*)e)[i];
}

// ---------------------------------------------------------------------------
__global__ void wprep_kernel(const float* W0, const float* W1, const float* W2,
                             const float* W3, const float* W4, const float* W5,
                             const float* Wi, const float* Wo,
                             const float* W1full, const float* W11full) {
    int gid = blockIdx.x * 256 + threadIdx.x;
    if (gid >= 18 * 16384) return;
    int m = gid >> 14, rem = gid & 16383;
    int k = rem >> 7, n = rem & 127;
    float v;
    if (m < 6) {
        const float* W = (m == 0) ? W0 : (m == 1) ? W1 : (m == 2) ? W2
                       : (m == 3) ? W3 : (m == 4) ? W4 : W5;
        v = W[k * 128 + n];
    } else if (m < 10) {
        v = Wi[k * FFH + (m - 6) * 128 + n];
    } else if (m < 14) {
        v = Wo[((m - 10) * 128 + k) * 128 + n];
    } else if (m == 14) {
        v = W1full[k * 128 + n];
    } else if (m == 15) {
        v = W1full[(256 + k) * 128 + n];
    } else if (m == 16) {
        v = W11full[k * 128 + n];
    } else {
        v = W11full[(256 + k) * 128 + n];
    }
    char* basep = (char*)g_Wb + (size_t)m * 34816;
    *(__half*)(basep + (uint32_t)k * 272u + (uint32_t)n * 2u) = __float2half_rn(v);
}

// ---------------------------------------------------------------------------
__device__ __forceinline__ void copyB_async(uint32_t dst, int mat) {
    const uint4* src = &g_Wb[(size_t)mat * 2176];
    #pragma unroll
    for (int i = 0; i < 9; i++) {
        int idx = threadIdx.x + 256*i;
        if (idx < 2176) cp16(dst + idx*16, src + idx);
    }
}

__device__ __forceinline__ void mma_layer64(uint32_t sb, int warpM, int warpN,
                                            int lane, float (&acc)[2][4][4]) {
    #pragma unroll
    for (int m = 0; m < 2; m++)
        #pragma unroll
        for (int j = 0; j < 4; j++)
            #pragma unroll
            for (int c = 0; c < 4; c++) acc[m][j][c] = 0.0f;

    uint32_t aA = sb + M_A + (uint32_t)(warpM*32 + (lane & 15))*AST
                + (uint32_t)(lane >> 4)*16;
    uint32_t bB = sb + M_B + (uint32_t)(lane & 15)*AST
                + (uint32_t)(warpN*4 + (lane >> 4))*16;

    #pragma unroll
    for (int ks = 0; ks < 8; ks++) {
        uint32_t ah0[4], ah1[4];
        ldm4(ah0, aA + ks*32);
        ldm4(ah1, aA + ks*32 + 16*AST);
        #pragma unroll
        for (int ng = 0; ng < 2; ng++) {
            uint32_t bh[4];
            ldm4t(bh, bB + ks*16*AST + ng*32);
            mma_f16(acc[0][2*ng],   ah0, bh[0], bh[1]);
            mma_f16(acc[1][2*ng],   ah1, bh[0], bh[1]);
            mma_f16(acc[0][2*ng+1], ah0, bh[2], bh[3]);
            mma_f16(acc[1][2*ng+1], ah1, bh[2], bh[3]);
        }
    }
}

__device__ __forceinline__ void loadA64(char* sm, const float* src, int tid) {
    for (int idx = tid; idx < 64*64; idx += 256) {
        int r = idx >> 6, cp = idx & 63;
        float2 x = *(const float2*)&src[(size_t)r*NH + cp*2];
        *(uint32_t*)(sm + M_A + r*AST + cp*4) = pack_f16(x.x, x.y);
    }
}

__device__ __forceinline__ void loadA64_cached(uint32_t sb, const uint32_t* cache,
                                               size_t row0, int tid) {
    #pragma unroll
    for (int i = 0; i < 4; i++) {
        int idx = tid + 256*i;
        int r = idx >> 4, q4 = (idx & 15) * 4;
        cp16(sb + M_A + r*AST + q4*4, &cache[(row0 + r)*64 + q4]);
    }
}

// ---------------------------------------------------------------------------
// tokenPG fused: P = A@W14 + b ; G = A@W15. grid 64.
// ---------------------------------------------------------------------------
__global__ void __launch_bounds__(256, 3) tokenPG_kernel(
    const float* __restrict__ A, const float* __restrict__ bias,
    float* __restrict__ P, float* __restrict__ G)
{
    extern __shared__ char sm[];
    uint32_t sb = smem_u32(sm);
    int tid = threadIdx.x;
    int wid = tid >> 5, lane = tid & 31;
    int warpM = wid & 1, warpN = wid >> 1;
    int qr = lane >> 2, qc = lane & 3;
    int bl0 = blockIdx.x * 64;
    int cBase = warpN*32 + 2*qc;

    copyB_async(sb + M_B, 14);
    CP_COMMIT();
    loadA64(sm, A + (size_t)bl0*NH, tid);
    CP_WAIT0();
    __syncthreads();

    float acc[2][4][4];
    mma_layer64(sb, warpM, warpN, lane, acc);
    __syncthreads();
    copyB_async(sb + M_B, 15);
    CP_COMMIT();

    #pragma unroll
    for (int mf = 0; mf < 2; mf++)
        #pragma unroll
        for (int j = 0; j < 4; j++) {
            int C = cBase + j*8;
            float2 bv = *(const float2*)&bias[C];
            #pragma unroll
            for (int h = 0; h < 2; h++) {
                int R = warpM*32 + mf*16 + h*8 + qr;
                float2 o2;
                o2.x = acc[mf][j][2*h+0] + bv.x;
                o2.y = acc[mf][j][2*h+1] + bv.y;
                *(float2*)&P[(size_t)(bl0 + R)*NH + C] = o2;
            }
        }
    CP_WAIT0();
    __syncthreads();

    mma_layer64(sb, warpM, warpN, lane, acc);
    #pragma unroll
    for (int mf = 0; mf < 2; mf++)
        #pragma unroll
        for (int j = 0; j < 4; j++) {
            int C = cBase + j*8;
            #pragma unroll
            for (int h = 0; h < 2; h++) {
                int R = warpM*32 + mf*16 + h*8 + qr;
                float2 o2;
                o2.x = acc[mf][j][2*h+0];
                o2.y = acc[mf][j][2*h+1];
                *(float2*)&G[(size_t)(bl0 + R)*NH + C] = o2;
            }
        }
}

// ---------------------------------------------------------------------------
// mlp3: 64 edge rows per CTA, occ=4. MODE 0 = node (2 layers + mma GEMV
// masked row-sum; writes hE fp16 cache). MODE 1 = edge (3 layers + LN3).
// ---------------------------------------------------------------------------
template<int MODE>
__global__ void __launch_bounds__(256, 4) mlp3_kernel(
    const float* __restrict__ hE,
    const float* __restrict__ P, const float* __restrict__ G,
    const float* __restrict__ bias2, const float* __restrict__ bias3,
    const float* __restrict__ mask_attend,
    const float* __restrict__ ln3s, const float* __restrict__ ln3b,
    float* __restrict__ out_hE, int matBase)
{
    extern __shared__ char sm[];
    uint32_t sb = smem_u32(sm);

    int tid = threadIdx.x;
    int wid = tid >> 5, lane = tid & 31;
    int warpM = wid & 1, warpN = wid >> 1;
    int qr = lane >> 2, qc = lane & 3;
    int e0 = blockIdx.x * 64;
    int cBase = warpN*32 + 2*qc;

    int Row[2][2];
    #pragma unroll
    for (int mf = 0; mf < 2; mf++)
        #pragma unroll
        for (int h = 0; h < 2; h++)
            Row[mf][h] = warpM*32 + mf*16 + h*8 + qr;

    copyB_async(sb + M_B, matBase + 0);
    if (MODE == 0) {
        CP_COMMIT();
        for (int idx = tid; idx < 64*64; idx += 256) {
            int r = idx >> 6, cp = idx & 63;
            float2 x = *(const float2*)&hE[(size_t)(e0 + r)*NH + cp*2];
            uint32_t u = pack_f16(x.x, x.y);
            *(uint32_t*)(sm + M_A + r*AST + cp*4) = u;
            g_hEf16[(size_t)(e0 + r)*64 + cp] = u;
        }
    } else {
        loadA64_cached(sb, g_hEf16, (size_t)e0, tid);
        CP_COMMIT();
    }
    {
        int r = tid >> 2, ln = tid & 3;
        int e = e0 + r;
        int tok = e / 48;
        int batch = (e >= NL*NK) ? 1 : 0;
        PREF_L2(&P[(size_t)tok*NH + ln*32]);
        PREF_L2(&G[(size_t)(batch*NL + g_idx32[e])*NH + ln*32]);
    }
    CP_WAIT0();
    __syncthreads();

    float acc[2][4][4];

    // ---- layer 1 ----
    mma_layer64(sb, warpM, warpN, lane, acc);
    __syncthreads();
    copyB_async(sb + M_B, matBase + 1);
    CP_COMMIT();
    {
        const float* Pr[2][2];
        const float* Gr[2][2];
        #pragma unroll
        for (int mf = 0; mf < 2; mf++)
            #pragma unroll
            for (int h = 0; h < 2; h++) {
                int e = e0 + Row[mf][h];
                int tok = e / 48;
                int batch = (e >= NL*NK) ? 1 : 0;
                Pr[mf][h] = P + (size_t)tok * NH;
                Gr[mf][h] = G + (size_t)(batch*NL + g_idx32[e]) * NH;
            }
        #pragma unroll
        for (int mf = 0; mf < 2; mf++)
            #pragma unroll
            for (int j = 0; j < 4; j++) {
                int C = cBase + j*8;
                #pragma unroll
                for (int h = 0; h < 2; h++) {
                    float2 pv = *(const float2*)&Pr[mf][h][C];
                    float2 gv = *(const float2*)&Gr[mf][h][C];
                    float v0 = gelu_f(acc[mf][j][2*h+0] + pv.x + gv.x);
                    float v1 = gelu_f(acc[mf][j][2*h+1] + pv.y + gv.y);
                    int R = Row[mf][h];
                    *(uint32_t*)(sm + M_A + R*AST + C*2) = pack_f16(v0, v1);
                }
            }
    }
    CP_WAIT0();
    __syncthreads();

    // ---- layer 2 ----
    mma_layer64(sb, warpM, warpN, lane, acc);
    __syncthreads();

    if (MODE == 0) {
        #pragma unroll
        for (int mf = 0; mf < 2; mf++)
            #pragma unroll
            for (int h = 0; h < 2; h++) {
                int R = Row[mf][h];
                float mk = mask_attend[e0 + R];
                #pragma unroll
                for (int j = 0; j < 4; j++) {
                    int C = cBase + j*8;
                    float2 bv = *(const float2*)&bias2[C];
                    float v0 = gelu_f(acc[mf][j][2*h+0] + bv.x) * mk;
                    float v1 = gelu_f(acc[mf][j][2*h+1] + bv.y) * mk;
                    *(uint32_t*)(sm + M_A + R*AST + C*2) = pack_f16(v0, v1);
                }
            }
        int t0 = e0 / 48;
        for (int i = tid; i < 16*64; i += 256) {
            int r = i >> 6, el = i & 63;
            float mval = 0.0f;
            if (r < 2 && ((e0 + el) / 48 - t0) == r)
                mval = 1.0f;
            *(__half*)(sm + M_B + r*MST + el*2) = __float2half_rn(mval);
        }
        __syncthreads();
        if (warpM == 0) {
            float sacc[4][4];
            #pragma unroll
            for (int j = 0; j < 4; j++)
                #pragma unroll
                for (int c = 0; c < 4; c++) sacc[j][c] = 0.0f;
            uint32_t aM = sb + M_B + (uint32_t)(lane & 15)*MST
                        + (uint32_t)(lane >> 4)*16;
            uint32_t bZ = sb + M_A + (uint32_t)(lane & 15)*AST
                        + (uint32_t)(warpN*4 + (lane >> 4))*16;
            #pragma unroll
            for (int kc = 0; kc < 4; kc++) {
                uint32_t am[4];
                ldm4(am, aM + kc*32);
                #pragma unroll
                for (int ng = 0; ng < 2; ng++) {
                    uint32_t bh[4];
                    ldm4t(bh, bZ + kc*16*AST + ng*32);
                    mma_f16(sacc[2*ng],   am, bh[0], bh[1]);
                    mma_f16(sacc[2*ng+1], am, bh[2], bh[3]);
                }
            }
            if (qr < 2) {
                int t = t0 + qr;
                float* dst;
                if (qr == 0)
                    dst = (t0*48 >= e0) ? &g_partA[(size_t)t*NH]
                                        : &g_partB[(size_t)t*NH];
                else
                    dst = &g_partA[(size_t)t*NH];
                #pragma unroll
                for (int j = 0; j < 4; j++) {
                    int col = warpN*32 + j*8 + qc*2;
                    *(float2*)&dst[col] = make_float2(sacc[j][0], sacc[j][1]);
                }
            }
        }
        return;
    }

    // ---- edge path ----
    copyB_async(sb + M_B, matBase + 2);
    CP_COMMIT();
    #pragma unroll
    for (int mf = 0; mf < 2; mf++)
        #pragma unroll
        for (int j = 0; j < 4; j++) {
            int C = cBase + j*8;
            float2 bv = *(const float2*)&bias2[C];
            #pragma unroll
            for (int h = 0; h < 2; h++) {
                float v0 = gelu_f(acc[mf][j][2*h+0] + bv.x);
                float v1 = gelu_f(acc[mf][j][2*h+1] + bv.y);
                int R = Row[mf][h];
                *(uint32_t*)(sm + M_A + R*AST + C*2) = pack_f16(v0, v1);
            }
        }
    {
        int r = tid >> 2, ln = tid & 3;
        PREF_L2(&hE[(size_t)(e0 + r)*NH + ln*32]);
    }
    CP_WAIT0();
    __syncthreads();

    mma_layer64(sb, warpM, warpN, lane, acc);
    __syncthreads();

    float* stats = (float*)(sm + M_STAT);
    float s1[2][2], s2[2][2];
    #pragma unroll
    for (int mf = 0; mf < 2; mf++)
        #pragma unroll
        for (int h = 0; h < 2; h++) { s1[mf][h] = 0.f; s2[mf][h] = 0.f; }
    #pragma unroll
    for (int mf = 0; mf < 2; mf++)
        #pragma unroll
        for (int j = 0; j < 4; j++) {
            int C = cBase + j*8;
            float2 bv = *(const float2*)&bias3[C];
            #pragma unroll
            for (int h = 0; h < 2; h++) {
                int R = Row[mf][h];
                float2 he = *(const float2*)&hE[(size_t)(e0 + R)*NH + C];
                float v0 = acc[mf][j][2*h+0] + bv.x + he.x;
                float v1 = acc[mf][j][2*h+1] + bv.y + he.y;
                acc[mf][j][2*h+0] = v0;
                acc[mf][j][2*h+1] = v1;
                s1[mf][h] += v0 + v1;
                s2[mf][h] += v0*v0 + v1*v1;
            }
        }
    #pragma unroll
    for (int mf = 0; mf < 2; mf++)
        #pragma unroll
        for (int h = 0; h < 2; h++) {
            #pragma unroll
            for (int o = 1; o < 4; o <<= 1) {
                s1[mf][h] += __shfl_xor_sync(0xffffffffu, s1[mf][h], o);
                s2[mf][h] += __shfl_xor_sync(0xffffffffu, s2[mf][h], o);
            }
            if (qc == 0) {
                stats[(warpN*64 + Row[mf][h])*2 + 0] = s1[mf][h];
                stats[(warpN*64 + Row[mf][h])*2 + 1] = s2[mf][h];
            }
        }
    __syncthreads();
    #pragma unroll
    for (int mf = 0; mf < 2; mf++)
        #pragma unroll
        for (int h = 0; h < 2; h++) {
            int R = Row[mf][h];
            float S1 = 0.f, S2 = 0.f;
            #pragma unroll
            for (int g = 0; g < 4; g++) {
                S1 += stats[(g*64 + R)*2 + 0];
                S2 += stats[(g*64 + R)*2 + 1];
            }
            float mu = S1 * (1.0f / NH);
            float var = S2 * (1.0f / NH) - mu * mu;
            float rinv = rsqrtf(var + 1e-5f);
            #pragma unroll
            for (int j = 0; j < 4; j++) {
                int C = cBase + j*8;
                float2 gs = *(const float2*)&ln3s[C];
                float2 gb = *(const float2*)&ln3b[C];
                float2 o2;
                o2.x = (acc[mf][j][2*h+0] - mu) * rinv * gs.x + gb.x;
                o2.y = (acc[mf][j][2*h+1] - mu) * rinv * gs.y + gb.y;
                *(float2*)&out_hE[(size_t)(e0 + R)*NH + C] = o2;
            }
        }
}

// ---------------------------------------------------------------------------
// nodeFin: dh = S@W3 + (Σmask)*b3 ; h1 = LN1(hV + dh/30). 64 tokens/CTA.
// ---------------------------------------------------------------------------
__global__ void __launch_bounds__(256) nodeFin_kernel(
    const float* __restrict__ hV, const float* __restrict__ b3,
    const float* __restrict__ mask_attend,
    const float* __restrict__ ln1s, const float* __restrict__ ln1b)
{
    extern __shared__ char sm[];
    uint32_t sb = smem_u32(sm);
    int tid = threadIdx.x;
    int wid = tid >> 5, lane = tid & 31;
    int warpM = wid & 1, warpN = wid >> 1;
    int qr = lane >> 2, qc = lane & 3;
    int bl0 = blockIdx.x * 64;
    int cBase = warpN*32 + 2*qc;

    copyB_async(sb + M_B, 2);
    CP_COMMIT();
    for (int idx = tid; idx < 64*64; idx += 256) {
        int r = idx >> 6, cp = idx & 63;
        int t = bl0 + r;
        float2 x = *(const float2*)&g_partA[(size_t)t*NH + cp*2];
        int s0 = t * 48;
        if (s0 / 64 != (s0 + 47) / 64) {
            float2 y = *(const float2*)&g_partB[(size_t)t*NH + cp*2];
            x.x += y.x; x.y += y.y;
        }
        *(uint32_t*)(sm + M_A + r*AST + cp*4) = pack_f16(x.x, x.y);
    }
    CP_WAIT0();
    __syncthreads();

    float acc[2][4][4];
    mma_layer64(sb, warpM, warpN, lane, acc);

    float* stats = (float*)(sm + M_STAT);
    float* msum  = (float*)(sm + M_STAT + 2048);
    if (tid < 64) {
        int t = bl0 + tid;
        float s = 0.0f;
        #pragma unroll 4
        for (int k = 0; k < NK; k += 4) {
            float4 m4 = *(const float4*)&mask_attend[t*NK + k];
            s += m4.x + m4.y + m4.z + m4.w;
        }
        msum[tid] = s;
    }
    __syncthreads();

    int Row[2][2];
    #pragma unroll
    for (int mf = 0; mf < 2; mf++)
        #pragma unroll
        for (int h = 0; h < 2; h++)
            Row[mf][h] = warpM*32 + mf*16 + h*8 + qr;

    float s1[2][2], s2[2][2];
    #pragma unroll
    for (int mf = 0; mf < 2; mf++)
        #pragma unroll
        for (int h = 0; h < 2; h++) { s1[mf][h] = 0.f; s2[mf][h] = 0.f; }

    #pragma unroll
    for (int mf = 0; mf < 2; mf++)
        #pragma unroll
        for (int j = 0; j < 4; j++) {
            int C = cBase + j*8;
            float2 bv = *(const float2*)&b3[C];
            #pragma unroll
            for (int h = 0; h < 2; h++) {
                int R = Row[mf][h];
                int t = bl0 + R;
                float ms = msum[R];
                float2 hv = *(const float2*)&hV[(size_t)t*NH + C];
                float v0 = hv.x + (acc[mf][j][2*h+0] + ms*bv.x) * (1.0f/30.0f);
                float v1 = hv.y + (acc[mf][j][2*h+1] + ms*bv.y) * (1.0f/30.0f);
                acc[mf][j][2*h+0] = v0;
                acc[mf][j][2*h+1] = v1;
                s1[mf][h] += v0 + v1;
                s2[mf][h] += v0*v0 + v1*v1;
            }
        }
    #pragma unroll
    for (int mf = 0; mf < 2; mf++)
        #pragma unroll
        for (int h = 0; h < 2; h++) {
            #pragma unroll
            for (int o = 1; o < 4; o <<= 1) {
                s1[mf][h] += __shfl_xor_sync(0xffffffffu, s1[mf][h], o);
                s2[mf][h] += __shfl_xor_sync(0xffffffffu, s2[mf][h], o);
            }
            if (qc == 0) {
                stats[(warpN*64 + Row[mf][h])*2 + 0] = s1[mf][h];
                stats[(warpN*64 + Row[mf][h])*2 + 1] = s2[mf][h];
            }
        }
    __syncthreads();
    #pragma unroll
    for (int mf = 0; mf < 2; mf++)
        #pragma unroll
        for (int h = 0; h < 2; h++) {
            int R = Row[mf][h];
            float S1 = 0.f, S2 = 0.f;
            #pragma unroll
            for (int g = 0; g < 4; g++) {
                S1 += stats[(g*64 + R)*2 + 0];
                S2 += stats[(g*64 + R)*2 + 1];
            }
            float mu = S1 * (1.0f / NH);
            float var = S2 * (1.0f / NH) - mu * mu;
            float rinv = rsqrtf(var + 1e-5f);
            #pragma unroll
            for (int j = 0; j < 4; j++) {
                int C = cBase + j*8;
                float2 gs = *(const float2*)&ln1s[C];
                float2 gb = *(const float2*)&ln1b[C];
                float2 o2;
                o2.x = (acc[mf][j][2*h+0] - mu) * rinv * gs.x + gb.x;
                o2.y = (acc[mf][j][2*h+1] - mu) * rinv * gs.y + gb.y;
                *(float2*)&g_h1[(size_t)(bl0 + R)*NH + C] = o2;
                g_h1f16[(size_t)(bl0 + R)*64 + (C >> 1)] = pack_f16(o2.x, o2.y);
            }
        }
}

// ---------------------------------------------------------------------------
// ffn1 (mma): H tile [64tok x 128col] = gelu(h1 @ Wi + bi), fp16 out.
// grid (64, 4).
// ---------------------------------------------------------------------------
__global__ void __launch_bounds__(256, 3) ffn1_kernel(const float* __restrict__ bi)
{
    extern __shared__ char sm[];
    uint32_t sb = smem_u32(sm);
    int tid = threadIdx.x;
    int wid = tid >> 5, lane = tid & 31;
    int warpM = wid & 1, warpN = wid >> 1;
    int qr = lane >> 2, qc = lane & 3;
    int bl0 = blockIdx.x * 64;
    int nb  = blockIdx.y * 128;
    int cBase = warpN*32 + 2*qc;

    copyB_async(sb + M_B, 6 + blockIdx.y);
    loadA64_cached(sb, g_h1f16, (size_t)bl0, tid);
    CP_COMMIT();
    CP_WAIT0();
    __syncthreads();

    float acc[2][4][4];
    mma_layer64(sb, warpM, warpN, lane, acc);

    #pragma unroll
    for (int mf = 0; mf < 2; mf++)
        #pragma unroll
        for (int j = 0; j < 4; j++) {
            int C = cBase + j*8;
            float2 bv = *(const float2*)&bi[nb + C];
            #pragma unroll
            for (int h = 0; h < 2; h++) {
                int R = warpM*32 + mf*16 + h*8 + qr;
                float v0 = gelu_f(acc[mf][j][2*h+0] + bv.x);
                float v1 = gelu_f(acc[mf][j][2*h+1] + bv.y);
                uint32_t gi = ((uint32_t)(bl0 + R)*FFH + nb + C) >> 1;
                g_Hhi[gi] = pack_f16(v0, v1);
            }
        }
}

// ---------------------------------------------------------------------------
// ffn2 (mma): hV2 = LN2(h1 + H @ Wo + bo) * mask_V, then fused
// P2 = hV2@W11P + b11, G2 = hV2@W11G. 32 tok/CTA, grid 128.
// ---------------------------------------------------------------------------
#define F2_A   0
#define F2_B   8704
#define F2_STAT 43520
#define SMEM_F2 45568

__device__ __forceinline__ void mma_32(uint32_t sb, int warpM, int warpN,
                                       int lane, float (&acc)[4][4]) {
    #pragma unroll
    for (int j = 0; j < 4; j++)
        #pragma unroll
        for (int c = 0; c < 4; c++) acc[j][c] = 0.0f;
    uint32_t aA = sb + F2_A + (uint32_t)(warpM*16 + (lane & 15))*AST
                + (uint32_t)(lane >> 4)*16;
    uint32_t bB = sb + F2_B + (uint32_t)(lane & 15)*AST
                + (uint32_t)(warpN*4 + (lane >> 4))*16;
    #pragma unroll
    for (int ks = 0; ks < 8; ks++) {
        uint32_t ah[4];
        ldm4(ah, aA + ks*32);
        #pragma unroll
        for (int ng = 0; ng < 2; ng++) {
            uint32_t bh[4];
            ldm4t(bh, bB + ks*16*AST + ng*32);
            mma_f16(acc[2*ng],   ah, bh[0], bh[1]);
            mma_f16(acc[2*ng+1], ah, bh[2], bh[3]);
        }
    }
}

__global__ void __launch_bounds__(256) ffn2_kernel(
    const float* __restrict__ bo,
    const float* __restrict__ ln2s, const float* __restrict__ ln2b,
    const float* __restrict__ mask_V, const float* __restrict__ b11,
    float* __restrict__ out_hV, float* __restrict__ P2, float* __restrict__ G2)
{
    extern __shared__ char sm[];
    uint32_t sb = smem_u32(sm);
    int tid = threadIdx.x;
    int wid = tid >> 5, lane = tid & 31;
    int warpM = wid & 1, warpN = wid >> 1;
    int qr = lane >> 2, qc = lane & 3;
    int bl0 = blockIdx.x * 32;
    int cBase = warpN*32 + 2*qc;

    float acc[4][4];
    #pragma unroll
    for (int j = 0; j < 4; j++)
        #pragma unroll
        for (int c = 0; c < 4; c++) acc[j][c] = 0.0f;

    for (int ch = 0; ch < 4; ch++) {
        {
            int idx = tid;
            #pragma unroll
            for (int i = 0; i < 2; i++) {
                int r = idx >> 4, q4 = (idx & 15) * 4;
                uint32_t gi = (uint32_t)(bl0 + r)*256 + ch*64 + q4;
                cp16(sb + F2_A + r*AST + q4*4, &g_Hhi[gi]);
                idx += 256;
            }
        }
        copyB_async(sb + F2_B, 10 + ch);
        CP_COMMIT();
        CP_WAIT0();
        __syncthreads();

        uint32_t aA = sb + F2_A + (uint32_t)(warpM*16 + (lane & 15))*AST
                    + (uint32_t)(lane >> 4)*16;
        uint32_t bB = sb + F2_B + (uint32_t)(lane & 15)*AST
                    + (uint32_t)(warpN*64 + (lane >> 4)*16);

        #pragma unroll
        for (int ks = 0; ks < 8; ks++) {
            uint32_t ah[4];
            ldm4(ah, aA + ks*32);
            #pragma unroll
            for (int ng = 0; ng < 2; ng++) {
                uint32_t bh[4];
                ldm4t(bh, bB + ks*16*AST + ng*32);
                mma_f16(acc[2*ng],   ah, bh[0], bh[1]);
                mma_f16(acc[2*ng+1], ah, bh[2], bh[3]);
            }
        }
        __syncthreads();
    }

    float* stats = (float*)(sm + F2_STAT);
    float s1[2], s2[2];
    #pragma unroll
    for (int h = 0; h < 2; h++) { s1[h] = 0.f; s2[h] = 0.f; }
    #pragma unroll
    for (int j = 0; j < 4; j++) {
        int C = cBase + j*8;
        float2 bv = *(const float2*)&bo[C];
        #pragma unroll
        for (int h = 0; h < 2; h++) {
            int R = warpM*16 + h*8 + qr;
            float2 hv = *(const float2*)&g_h1[(size_t)(bl0 + R)*NH + C];
            float v0 = acc[j][2*h+0] + bv.x + hv.x;
            float v1 = acc[j][2*h+1] + bv.y + hv.y;
            acc[j][2*h+0] = v0;
            acc[j][2*h+1] = v1;
            s1[h] += v0 + v1;
            s2[h] += v0*v0 + v1*v1;
        }
    }
    #pragma unroll
    for (int h = 0; h < 2; h++) {
        #pragma unroll
        for (int o = 1; o < 4; o <<= 1) {
            s1[h] += __shfl_xor_sync(0xffffffffu, s1[h], o);
            s2[h] += __shfl_xor_sync(0xffffffffu, s2[h], o);
        }
        if (qc == 0) {
            int R = warpM*16 + h*8 + qr;
            stats[(warpN*32 + R)*2 + 0] = s1[h];
            stats[(warpN*32 + R)*2 + 1] = s2[h];
        }
    }
    __syncthreads();
    #pragma unroll
    for (int h = 0; h < 2; h++) {
        int R = warpM*16 + h*8 + qr;
        float S1 = 0.f, S2 = 0.f;
        #pragma unroll
        for (int g = 0; g < 4; g++) {
            S1 += stats[(g*32 + R)*2 + 0];
            S2 += stats[(g*32 + R)*2 + 1];
        }
        float mu = S1 * (1.0f / NH);
        float var = S2 * (1.0f / NH) - mu * mu;
        float rinv = rsqrtf(var + 1e-5f);
        int token = bl0 + R;
        float mk = mask_V[token];
        #pragma unroll
        for (int j = 0; j < 4; j++) {
            int C = cBase + j*8;
            float2 gs = *(const float2*)&ln2s[C];
            float2 gb = *(const float2*)&ln2b[C];
            float2 o2;
            o2.x = ((acc[j][2*h+0] - mu) * rinv * gs.x + gb.x) * mk;
            o2.y = ((acc[j][2*h+1] - mu) * rinv * gs.y + gb.y) * mk;
            *(float2*)&out_hV[(size_t)token*NH + C] = o2;
            *(uint32_t*)(sm + F2_A + R*AST + C*2) = pack_f16(o2.x, o2.y);
        }
    }
    __syncthreads();

    copyB_async(sb + F2_B, 16);
    CP_COMMIT();
    CP_WAIT0();
    __syncthreads();
    float acc2[4][4];
    mma_32(sb, warpM, warpN, lane, acc2);
    #pragma unroll
    for (int j = 0; j < 4; j++) {
        int C = cBase + j*8;
        float2 bv = *(const float2*)&b11[C];
        #pragma unroll
        for (int h = 0; h < 2; h++) {
            int R = warpM*16 + h*8 + qr;
            float2 o2;
            o2.x = acc2[j][2*h+0] + bv.x;
            o2.y = acc2[j][2*h+1] + bv.y;
            *(float2*)&P2[(size_t)(bl0 + R)*NH + C] = o2;
        }
    }
    __syncthreads();

    copyB_async(sb + F2_B, 17);
    CP_COMMIT();
    CP_WAIT0();
    __syncthreads();
    mma_32(sb, warpM, warpN, lane, acc2);
    #pragma unroll
    for (int j = 0; j < 4; j++) {
        int C = cBase + j*8;
        #pragma unroll
        for (int h = 0; h < 2; h++) {
            int R = warpM*16 + h*8 + qr;
            float2 o2;
            o2.x = acc2[j][2*h+0];
            o2.y = acc2[j][2*h+1];
            *(float2*)&G2[(size_t)(bl0 + R)*NH + C] = o2;
        }
    }
}

// ---------------------------------------------------------------------------

extern "C" void kernel_launch(void* const* d_in, const int* in_sizes, int n_in,
                              void* d_out, int out_size)
{
    const float* h_V         = (const float*)d_in[0];
    const float* h_E         = (const float*)d_in[1];
    const void*  E_idx       =               d_in[2];
    const float* mask_V      = (const float*)d_in[3];
    const float* mask_attend = (const float*)d_in[4];
    const float* W1  = (const float*)d_in[5],  *b1  = (const float*)d_in[6];
    const float* W2  = (const float*)d_in[7],  *b2  = (const float*)d_in[8];
    const float* W3  = (const float*)d_in[9],  *b3  = (const float*)d_in[10];
    const float* W11 = (const float*)d_in[11], *b11 = (const float*)d_in[12];
    const float* W12 = (const float*)d_in[13], *b12 = (const float*)d_in[14];
    const float* W13 = (const float*)d_in[15], *b13 = (const float*)d_in[16];
    const float* Wi  = (const float*)d_in[17], *bi  = (const float*)d_in[18];
    const float* Wo  = (const float*)d_in[19], *bo  = (const float*)d_in[20];
    const float* ln1s = (const float*)d_in[21], *ln1b = (const float*)d_in[22];
    const float* ln2s = (const float*)d_in[23], *ln2b = (const float*)d_in[24];
    const float* ln3s = (const float*)d_in[25], *ln3b = (const float*)d_in[26];
    float* out = (float*)d_out;

    float *pP1, *pG1, *pP2, *pG2;
    cudaGetSymbolAddress((void**)&pP1,  g_P1);
    cudaGetSymbolAddress((void**)&pG1,  g_G1);
    cudaGetSymbolAddress((void**)&pP2,  g_P2);
    cudaGetSymbolAddress((void**)&pG2,  g_G2);

    cudaFuncSetAttribute(tokenPG_kernel, cudaFuncAttributeMaxDynamicSharedMemorySize, SMEM64);
    cudaFuncSetAttribute(ffn1_kernel,  cudaFuncAttributeMaxDynamicSharedMemorySize, SMEM64);
    cudaFuncSetAttribute(ffn2_kernel,  cudaFuncAttributeMaxDynamicSharedMemorySize, SMEM_F2);
    cudaFuncSetAttribute(nodeFin_kernel, cudaFuncAttributeMaxDynamicSharedMemorySize, SMEMNF);
    cudaFuncSetAttribute(mlp3_kernel<0>, cudaFuncAttributeMaxDynamicSharedMemorySize, SMEM64);
    cudaFuncSetAttribute(mlp3_kernel<1>, cudaFuncAttributeMaxDynamicSharedMemorySize, SMEM64);

    convert_kernel<<<(NEDGE + 255) / 256, 256>>>(E_idx);

    wprep_kernel<<<(18*16384 + 255)/256, 256>>>(W1 + 128*NH, W2, W3,
                                                W11 + 128*NH, W12, W13, Wi, Wo,
                                                W1, W11);

    tokenPG_kernel<<<64, 256, SMEM64>>>(h_V, b1, pP1, pG1);

    mlp3_kernel<0><<<NEDGE/64, 256, SMEM64>>>(h_E, pP1, pG1, b2, nullptr,
                                              mask_attend, nullptr, nullptr,
                                              nullptr, 0);
    nodeFin_kernel<<<64, 256, SMEMNF>>>(h_V, b3, mask_attend, ln1s, ln1b);

    ffn1_kernel<<<dim3(64, 4), 256, SMEM64>>>(bi);
    ffn2_kernel<<<128, 256, SMEM_F2>>>(bo, ln2s, ln2b, mask_V, b11,
                                       out, pP2, pG2);

    mlp3_kernel<1><<<NEDGE/64, 256, SMEM64>>>(h_E, pP2, pG2, b12, b13,
                                              nullptr, ln3s, ln3b,
                                              out + (size_t)NTOK * NH, 3);
}